// round 1
// baseline (speedup 1.0000x reference)
#include <cuda_runtime.h>
#include <math.h>

#define BB 8
#define CC 128
#define TT 8
#define HWD 1024
#define NPOS 8192      // TT*HWD
#define CT 1024        // CC*TT

// ---------------- scratch (static device globals; no allocation) ----------------
__device__ float g_qf[BB][128][HWD];          // row = cq*TT + t
__device__ float g_kf[BB][128][HWD];
__device__ float g_vf[BB][CT][HWD];           // row = c*TT + t
__device__ float g_attn[BB][HWD][HWD];        // energy -> softmax in place
__device__ float g_ecam_p[8][BB][CC][CC];     // K-split partials of CAM energy
__device__ float g_acam[BB][CC][CC];          // CAM attention (after softmax)
__device__ float g_etim_p[BB][CC][36];        // per-channel upper-tri TIM partials
__device__ float g_atim[BB][TT][TT];          // TIM attention

// ---------------- 1) fused q/k/v projection ----------------
// Combined-rows GEMM: rows 0..15 -> Wq, 16..31 -> Wk, 32..159 -> Wv.
// out[r, pos] = sum_c W[r][c] * x[b][c][pos] + bias[r]
__global__ __launch_bounds__(256) void k_qkv(
    const float* __restrict__ x,
    const float* __restrict__ Wq, const float* __restrict__ bq,
    const float* __restrict__ Wk, const float* __restrict__ bk,
    const float* __restrict__ Wv, const float* __restrict__ bv)
{
    int b    = blockIdx.z;
    int m0   = blockIdx.y * 32;     // 0..128 step 32 (5 tiles of 160)
    int pos0 = blockIdx.x * 64;
    __shared__ float Ws[32][33];
    __shared__ float Xs[32][65];
    int tid = threadIdx.x;
    int tx = tid & 15, ty = tid >> 4;
    float acc[2][4] = {};
    const float* xb = x + (size_t)b * (CC * NPOS);

    for (int kc = 0; kc < CC; kc += 32) {
#pragma unroll
        for (int q = 0; q < 4; q++) {
            int e = tid + q * 256;
            int i = e >> 5, k = e & 31;
            int r = m0 + i;
            float w;
            if (r < 16)       w = Wq[r * CC + kc + k];
            else if (r < 32)  w = Wk[(r - 16) * CC + kc + k];
            else              w = Wv[(r - 32) * CC + kc + k];
            Ws[i][k] = w;
        }
#pragma unroll
        for (int q = 0; q < 8; q++) {
            int e = tid + q * 256;
            int k = e >> 6, p = e & 63;
            Xs[k][p] = xb[(size_t)(kc + k) * NPOS + pos0 + p];
        }
        __syncthreads();
#pragma unroll
        for (int k = 0; k < 32; k++) {
            float a0 = Ws[ty][k], a1 = Ws[ty + 16][k];
#pragma unroll
            for (int ip = 0; ip < 4; ip++) {
                float xv = Xs[k][tx + 16 * ip];
                acc[0][ip] += a0 * xv;
                acc[1][ip] += a1 * xv;
            }
        }
        __syncthreads();
    }

    int t   = pos0 >> 10;
    int hw0 = pos0 & 1023;
#pragma unroll
    for (int jr = 0; jr < 2; jr++) {
        int r = m0 + ty + 16 * jr;
#pragma unroll
        for (int ip = 0; ip < 4; ip++) {
            int hw = hw0 + tx + 16 * ip;
            float v = acc[jr][ip];
            if (r < 16)       g_qf[b][r * TT + t][hw]        = v + bq[r];
            else if (r < 32)  g_kf[b][(r - 16) * TT + t][hw] = v + bk[r - 16];
            else              g_vf[b][(r - 32) * TT + t][hw] = v + bv[r - 32];
        }
    }
}

// ---------------- 2) PAM energy: E[n][m] = sum_f qf[f][n]*kf[f][m] ----------------
__global__ __launch_bounds__(256) void k_energy()
{
    int b  = blockIdx.z;
    int n0 = blockIdx.y * 64;
    int m0 = blockIdx.x * 64;
    __shared__ float Qs[32][65];
    __shared__ float Ks[32][65];
    int tid = threadIdx.x;
    int tx = tid & 15, ty = tid >> 4;
    float acc[4][4] = {};

    for (int kc = 0; kc < 128; kc += 32) {
#pragma unroll
        for (int q = 0; q < 8; q++) {
            int e = tid + q * 256;
            int k = e >> 6, i = e & 63;
            Qs[k][i] = g_qf[b][kc + k][n0 + i];
            Ks[k][i] = g_kf[b][kc + k][m0 + i];
        }
        __syncthreads();
#pragma unroll
        for (int k = 0; k < 32; k++) {
            float a[4], c[4];
#pragma unroll
            for (int j = 0; j < 4; j++) a[j] = Qs[k][ty + 16 * j];
#pragma unroll
            for (int j = 0; j < 4; j++) c[j] = Ks[k][tx + 16 * j];
#pragma unroll
            for (int jr = 0; jr < 4; jr++)
#pragma unroll
                for (int ic = 0; ic < 4; ic++) acc[jr][ic] += a[jr] * c[ic];
        }
        __syncthreads();
    }
#pragma unroll
    for (int jr = 0; jr < 4; jr++)
#pragma unroll
        for (int ic = 0; ic < 4; ic++)
            g_attn[b][n0 + ty + 16 * jr][m0 + tx + 16 * ic] = acc[jr][ic];
}

// ---------------- 3) row softmax over last dim of g_attn (8192 rows x 1024) ----------------
__global__ __launch_bounds__(256) void k_softmax()
{
    int row = blockIdx.x;
    float* e = &g_attn[0][0][0] + (size_t)row * 1024;
    int tid = threadIdx.x;
    float v[4];
    float m = -3.4e38f;
#pragma unroll
    for (int j = 0; j < 4; j++) { v[j] = e[tid + 256 * j]; m = fmaxf(m, v[j]); }
    __shared__ float red[8];
#pragma unroll
    for (int o = 16; o > 0; o >>= 1) m = fmaxf(m, __shfl_xor_sync(0xffffffffu, m, o));
    if ((tid & 31) == 0) red[tid >> 5] = m;
    __syncthreads();
    m = red[0];
#pragma unroll
    for (int j = 1; j < 8; j++) m = fmaxf(m, red[j]);
    float s = 0.f;
#pragma unroll
    for (int j = 0; j < 4; j++) { v[j] = __expf(v[j] - m); s += v[j]; }
    __syncthreads();
#pragma unroll
    for (int o = 16; o > 0; o >>= 1) s += __shfl_xor_sync(0xffffffffu, s, o);
    if ((tid & 31) == 0) red[tid >> 5] = s;
    __syncthreads();
    s = red[0];
#pragma unroll
    for (int j = 1; j < 8; j++) s += red[j];
    float inv = 1.f / s;
#pragma unroll
    for (int j = 0; j < 4; j++) e[tid + 256 * j] = v[j] * inv;
}

// ---------------- 4) CAM energy partials: e[c][d] = sum_n x[c,n]*x[d,n], K-split 8 ----------------
__global__ __launch_bounds__(256) void k_came(const float* __restrict__ x)
{
    int d0 = blockIdx.x * 64;
    int c0 = blockIdx.y * 64;
    int b  = blockIdx.z >> 3;
    int sl = blockIdx.z & 7;
    __shared__ float Xc[64][33];
    __shared__ float Xd[64][33];
    int tid = threadIdx.x;
    int tx = tid & 15, ty = tid >> 4;
    float acc[4][4] = {};
    const float* xb = x + (size_t)b * (CC * NPOS);
    int n_lo = sl * 1024;

    for (int nc = n_lo; nc < n_lo + 1024; nc += 32) {
#pragma unroll
        for (int q = 0; q < 8; q++) {
            int e = tid + q * 256;
            int i = e >> 5, k = e & 31;
            Xc[i][k] = xb[(size_t)(c0 + i) * NPOS + nc + k];
            Xd[i][k] = xb[(size_t)(d0 + i) * NPOS + nc + k];
        }
        __syncthreads();
#pragma unroll
        for (int k = 0; k < 32; k++) {
            float a[4], c[4];
#pragma unroll
            for (int j = 0; j < 4; j++) a[j] = Xc[ty + 16 * j][k];
#pragma unroll
            for (int j = 0; j < 4; j++) c[j] = Xd[tx + 16 * j][k];
#pragma unroll
            for (int jr = 0; jr < 4; jr++)
#pragma unroll
                for (int ic = 0; ic < 4; ic++) acc[jr][ic] += a[jr] * c[ic];
        }
        __syncthreads();
    }
#pragma unroll
    for (int jr = 0; jr < 4; jr++)
#pragma unroll
        for (int ic = 0; ic < 4; ic++)
            g_ecam_p[sl][b][c0 + ty + 16 * jr][d0 + tx + 16 * ic] = acc[jr][ic];
}

// ---------------- 5) CAM negated-energy softmax per row (1024 rows x 128) ----------------
__global__ __launch_bounds__(128) void k_camsm()
{
    int b = blockIdx.x >> 7;
    int c = blockIdx.x & 127;
    int d = threadIdx.x;
    float ev = 0.f;
#pragma unroll
    for (int sl = 0; sl < 8; sl++) ev += g_ecam_p[sl][b][c][d];
    __shared__ float red[4];
    float mn = ev;
#pragma unroll
    for (int o = 16; o > 0; o >>= 1) mn = fminf(mn, __shfl_xor_sync(0xffffffffu, mn, o));
    if ((threadIdx.x & 31) == 0) red[threadIdx.x >> 5] = mn;
    __syncthreads();
    mn = fminf(fminf(red[0], red[1]), fminf(red[2], red[3]));
    // softmax(rowmax - e) == exp(min - e)/sum(exp(min - e))
    float w = __expf(mn - ev);
    __syncthreads();
    float s = w;
#pragma unroll
    for (int o = 16; o > 0; o >>= 1) s += __shfl_xor_sync(0xffffffffu, s, o);
    if ((threadIdx.x & 31) == 0) red[threadIdx.x >> 5] = s;
    __syncthreads();
    s = (red[0] + red[1]) + (red[2] + red[3]);
    g_acam[b][c][d] = w / s;
}

// ---------------- 6) TIM energy partials: per (b,c) 8x8 Gram of t-rows (upper tri) ----------------
__global__ __launch_bounds__(256) void k_time(const float* __restrict__ x)
{
    int c = blockIdx.x;   // 0..127
    int b = blockIdx.y;
    int tid = threadIdx.x;
    const float* xp = x + ((size_t)b * CC + c) * NPOS;
    float v[8][4];
#pragma unroll
    for (int t = 0; t < 8; t++) {
        float4 f = *reinterpret_cast<const float4*>(xp + t * 1024 + tid * 4);
        v[t][0] = f.x; v[t][1] = f.y; v[t][2] = f.z; v[t][3] = f.w;
    }
    float acc[36];
    int idx = 0;
#pragma unroll
    for (int t = 0; t < 8; t++)
#pragma unroll
        for (int s = t; s < 8; s++) {
            float a = 0.f;
#pragma unroll
            for (int j = 0; j < 4; j++) a += v[t][j] * v[s][j];
            acc[idx++] = a;
        }
    __shared__ float red[36][8];
    int lane = tid & 31, warp = tid >> 5;
#pragma unroll
    for (int i = 0; i < 36; i++) {
        float a = acc[i];
#pragma unroll
        for (int o = 16; o > 0; o >>= 1) a += __shfl_xor_sync(0xffffffffu, a, o);
        if (lane == 0) red[i][warp] = a;
    }
    __syncthreads();
    if (tid < 36) {
        float a = 0.f;
#pragma unroll
        for (int w = 0; w < 8; w++) a += red[tid][w];
        g_etim_p[b][c][tid] = a;
    }
}

// ---------------- 7) reduce TIM partials + negated softmax (single block) ----------------
__global__ __launch_bounds__(256) void k_timsm()
{
    __shared__ float e36[BB][36];
    int tid = threadIdx.x;
    for (int o = tid; o < BB * 36; o += 256) {
        int b = o / 36, i = o % 36;
        float a = 0.f;
        for (int c = 0; c < CC; c++) a += g_etim_p[b][c][i];
        e36[b][i] = a;
    }
    __syncthreads();
    if (tid < 64) {
        int b = tid >> 3, t = tid & 7;
        float e[8];
#pragma unroll
        for (int s = 0; s < 8; s++) {
            int lo = t < s ? t : s, hi = t < s ? s : t;
            int idx = 8 * lo - lo * (lo - 1) / 2 + (hi - lo);
            e[s] = e36[b][idx];
        }
        float mn = e[0];
#pragma unroll
        for (int s = 1; s < 8; s++) mn = fminf(mn, e[s]);
        float w[8], sum = 0.f;
#pragma unroll
        for (int s = 0; s < 8; s++) { w[s] = __expf(mn - e[s]); sum += w[s]; }
#pragma unroll
        for (int s = 0; s < 8; s++) g_atim[b][t][s] = w[s] / sum;
    }
}

// ---------------- 8) base: out = 3x + gc*(a_cam @ xc) + gt*tim ----------------
__global__ __launch_bounds__(256) void k_base(
    const float* __restrict__ x,
    const float* __restrict__ gcp, const float* __restrict__ gtp,
    float* __restrict__ out)
{
    int b    = blockIdx.z;
    int c0   = blockIdx.y * 32;
    int pos0 = blockIdx.x * 64;
    int t    = pos0 >> 10;
    int hw0  = pos0 & 1023;
    __shared__ float As[32][33];
    __shared__ float Xs[32][65];
    __shared__ float at[8];
    int tid = threadIdx.x;
    if (tid < 8) at[tid] = g_atim[b][t][tid];
    int tx = tid & 15, ty = tid >> 4;
    float acc[2][4] = {};
    const float* xb = x + (size_t)b * (CC * NPOS);

    for (int kc = 0; kc < CC; kc += 32) {
#pragma unroll
        for (int q = 0; q < 4; q++) {
            int e = tid + q * 256;
            int i = e >> 5, k = e & 31;
            As[i][k] = g_acam[b][c0 + i][kc + k];
        }
#pragma unroll
        for (int q = 0; q < 8; q++) {
            int e = tid + q * 256;
            int k = e >> 6, p = e & 63;
            Xs[k][p] = xb[(size_t)(kc + k) * NPOS + pos0 + p];
        }
        __syncthreads();
#pragma unroll
        for (int k = 0; k < 32; k++) {
            float a0 = As[ty][k], a1 = As[ty + 16][k];
#pragma unroll
            for (int ip = 0; ip < 4; ip++) {
                float xv = Xs[k][tx + 16 * ip];
                acc[0][ip] += a0 * xv;
                acc[1][ip] += a1 * xv;
            }
        }
        __syncthreads();
    }

    float gc = gcp[0], gt = gtp[0];
#pragma unroll
    for (int jr = 0; jr < 2; jr++) {
        int c = c0 + ty + 16 * jr;
        const float* xc = xb + (size_t)c * NPOS;
#pragma unroll
        for (int ip = 0; ip < 4; ip++) {
            int hw = hw0 + tx + 16 * ip;
            float tim = 0.f;
#pragma unroll
            for (int s = 0; s < 8; s++) tim += at[s] * xc[s * 1024 + hw];
            float xv = xc[t * 1024 + hw];
            out[(size_t)b * (CC * NPOS) + (size_t)c * NPOS + t * 1024 + hw] =
                3.f * xv + gc * acc[jr][ip] + gt * tim;
        }
    }
}

// ---------------- 9) PAM NT GEMM: out += gp * (vf @ attn^T) ----------------
__global__ __launch_bounds__(256) void k_pam(const float* __restrict__ gpp,
                                             float* __restrict__ out)
{
    int b  = blockIdx.z;
    int r0 = blockIdx.y * 64;
    int n0 = blockIdx.x * 64;
    __shared__ float As[16][68];   // [k][row], padded: float4 reads stay aligned
    __shared__ float Bs[16][68];   // [k][col]
    int tid = threadIdx.x;
    int tx = tid & 15, ty = tid >> 4;
    const float* V = &g_vf[b][0][0];
    const float* A = &g_attn[b][0][0];
    float acc[4][4] = {};
    int li = tid >> 2;          // 0..63
    int lk = (tid & 3) * 4;     // 0,4,8,12

    for (int mc = 0; mc < 1024; mc += 16) {
        float4 va = *reinterpret_cast<const float4*>(V + (size_t)(r0 + li) * 1024 + mc + lk);
        float4 vb = *reinterpret_cast<const float4*>(A + (size_t)(n0 + li) * 1024 + mc + lk);
        As[lk + 0][li] = va.x; As[lk + 1][li] = va.y;
        As[lk + 2][li] = va.z; As[lk + 3][li] = va.w;
        Bs[lk + 0][li] = vb.x; Bs[lk + 1][li] = vb.y;
        Bs[lk + 2][li] = vb.z; Bs[lk + 3][li] = vb.w;
        __syncthreads();
#pragma unroll
        for (int k = 0; k < 16; k++) {
            float4 a4 = *reinterpret_cast<const float4*>(&As[k][ty * 4]);
            float4 b4 = *reinterpret_cast<const float4*>(&Bs[k][tx * 4]);
            float av[4] = {a4.x, a4.y, a4.z, a4.w};
            float bv[4] = {b4.x, b4.y, b4.z, b4.w};
#pragma unroll
            for (int j = 0; j < 4; j++)
#pragma unroll
                for (int i = 0; i < 4; i++) acc[j][i] += av[j] * bv[i];
        }
        __syncthreads();
    }

    float gp = gpp[0];
    float* ob = out + (size_t)b * (CT * HWD);
#pragma unroll
    for (int j = 0; j < 4; j++) {
        float4* p = reinterpret_cast<float4*>(ob + (size_t)(r0 + ty * 4 + j) * 1024 + n0 + tx * 4);
        float4 o = *p;
        o.x += gp * acc[j][0];
        o.y += gp * acc[j][1];
        o.z += gp * acc[j][2];
        o.w += gp * acc[j][3];
        *p = o;
    }
}

// ---------------- launch ----------------
extern "C" void kernel_launch(void* const* d_in, const int* in_sizes, int n_in,
                              void* d_out, int out_size)
{
    const float* x  = (const float*)d_in[0];
    const float* Wq = (const float*)d_in[1];
    const float* bq = (const float*)d_in[2];
    const float* Wk = (const float*)d_in[3];
    const float* bk = (const float*)d_in[4];
    const float* Wv = (const float*)d_in[5];
    const float* bv = (const float*)d_in[6];
    const float* gp = (const float*)d_in[7];
    const float* gc = (const float*)d_in[8];
    const float* gt = (const float*)d_in[9];
    float* out = (float*)d_out;

    k_qkv<<<dim3(128, 5, 8), 256>>>(x, Wq, bq, Wk, bk, Wv, bv);
    k_energy<<<dim3(16, 16, 8), 256>>>();
    k_softmax<<<8192, 256>>>();
    k_came<<<dim3(2, 2, 64), 256>>>(x);
    k_camsm<<<1024, 128>>>();
    k_time<<<dim3(128, 8), 256>>>(x);
    k_timsm<<<1, 256>>>();
    k_base<<<dim3(128, 4, 8), 256>>>(x, gc, gt, out);
    k_pam<<<dim3(16, 16, 8), 256>>>(gp, out);
}

// round 3
// speedup vs baseline: 1.5455x; 1.5455x over previous
#include <cuda_runtime.h>
#include <cuda_bf16.h>
#include <math.h>
#include <stdint.h>

#define BB 8
#define CC 128
#define TT 8
#define HWD 1024
#define NPOS 8192
#define CT 1024

// ---------------- scratch ----------------
__device__ float g_qf[BB][128][HWD];
__device__ float g_kf[BB][128][HWD];
__device__ __nv_bfloat16 g_vf_h[BB][CT][HWD];
__device__ __nv_bfloat16 g_vf_l[BB][CT][HWD];
__device__ float g_attn[BB][HWD][HWD];                // energy (softmax input)
__device__ __nv_bfloat16 g_attn_h[BB][HWD][HWD];
__device__ __nv_bfloat16 g_attn_l[BB][HWD][HWD];
__device__ float g_ecam_p[16][BB][CC][CC];
__device__ float g_acam[BB][CC][CC];
__device__ float g_etim_p[BB][CC][36];
__device__ float g_atim[BB][TT][TT];

// ---------------- mma.sync helper (base ISA, valid on sm_103) ----------------
__device__ __forceinline__ void mma16816(float* c, const uint32_t* a, const uint32_t* b) {
    asm volatile(
        "mma.sync.aligned.m16n8k16.row.col.f32.bf16.bf16.f32 "
        "{%0,%1,%2,%3}, {%4,%5,%6,%7}, {%8,%9}, {%0,%1,%2,%3};"
        : "+f"(c[0]), "+f"(c[1]), "+f"(c[2]), "+f"(c[3])
        : "r"(a[0]), "r"(a[1]), "r"(a[2]), "r"(a[3]), "r"(b[0]), "r"(b[1]));
}

// ---------------- 1) fused q/k/v projection (64 rows x 128 pos tile) ----------------
__global__ __launch_bounds__(256) void k_qkv(
    const float* __restrict__ x,
    const float* __restrict__ Wq, const float* __restrict__ bq,
    const float* __restrict__ Wk, const float* __restrict__ bk,
    const float* __restrict__ Wv, const float* __restrict__ bv)
{
    int b    = blockIdx.z;
    int m0   = blockIdx.y * 64;      // 0,64,128 (rows of 160)
    int pos0 = blockIdx.x * 128;
    __shared__ float Ws[64][33];
    __shared__ float Xs[32][129];
    int tid = threadIdx.x;
    int tx = tid & 15, ty = tid >> 4;
    float acc[4][8] = {};
    const float* xb = x + (size_t)b * (CC * NPOS);

    for (int kc = 0; kc < CC; kc += 32) {
#pragma unroll
        for (int q = 0; q < 8; q++) {
            int e = tid + q * 256;
            int i = e >> 5, k = e & 31;
            int r = m0 + i;
            float w = 0.f;
            if (r < 16)       w = Wq[r * CC + kc + k];
            else if (r < 32)  w = Wk[(r - 16) * CC + kc + k];
            else if (r < 160) w = Wv[(r - 32) * CC + kc + k];
            Ws[i][k] = w;
        }
#pragma unroll
        for (int q = 0; q < 16; q++) {
            int e = tid + q * 256;
            int k = e >> 7, p = e & 127;
            Xs[k][p] = xb[(size_t)(kc + k) * NPOS + pos0 + p];
        }
        __syncthreads();
#pragma unroll
        for (int k = 0; k < 32; k++) {
            float a[4], xv[8];
#pragma unroll
            for (int j = 0; j < 4; j++) a[j] = Ws[ty + 16 * j][k];
#pragma unroll
            for (int i = 0; i < 8; i++) xv[i] = Xs[k][tx + 16 * i];
#pragma unroll
            for (int j = 0; j < 4; j++)
#pragma unroll
                for (int i = 0; i < 8; i++) acc[j][i] += a[j] * xv[i];
        }
        __syncthreads();
    }

    int t   = pos0 >> 10;
    int hw0 = pos0 & 1023;
#pragma unroll
    for (int j = 0; j < 4; j++) {
        int r = m0 + ty + 16 * j;
        if (r >= 160) continue;
#pragma unroll
        for (int i = 0; i < 8; i++) {
            int hw = hw0 + tx + 16 * i;
            float v = acc[j][i];
            if (r < 16)       g_qf[b][r * TT + t][hw] = v + bq[r];
            else if (r < 32)  g_kf[b][(r - 16) * TT + t][hw] = v + bk[r - 16];
            else {
                float vv = v + bv[r - 32];
                __nv_bfloat16 hi = __float2bfloat16(vv);
                __nv_bfloat16 lo = __float2bfloat16(vv - __bfloat162float(hi));
                int row = (r - 32) * TT + t;
                g_vf_h[b][row][hw] = hi;
                g_vf_l[b][row][hw] = lo;
            }
        }
    }
}

// ---------------- 2) PAM energy: E[n][m] = sum_f qf[f][n]*kf[f][m] ----------------
__global__ __launch_bounds__(256) void k_energy()
{
    int b  = blockIdx.z;
    int n0 = blockIdx.y * 64;
    int m0 = blockIdx.x * 64;
    __shared__ float Qs[32][65];
    __shared__ float Ks[32][65];
    int tid = threadIdx.x;
    int tx = tid & 15, ty = tid >> 4;
    float acc[4][4] = {};

    for (int kc = 0; kc < 128; kc += 32) {
#pragma unroll
        for (int q = 0; q < 8; q++) {
            int e = tid + q * 256;
            int k = e >> 6, i = e & 63;
            Qs[k][i] = g_qf[b][kc + k][n0 + i];
            Ks[k][i] = g_kf[b][kc + k][m0 + i];
        }
        __syncthreads();
#pragma unroll
        for (int k = 0; k < 32; k++) {
            float a[4], c[4];
#pragma unroll
            for (int j = 0; j < 4; j++) a[j] = Qs[k][ty + 16 * j];
#pragma unroll
            for (int j = 0; j < 4; j++) c[j] = Ks[k][tx + 16 * j];
#pragma unroll
            for (int jr = 0; jr < 4; jr++)
#pragma unroll
                for (int ic = 0; ic < 4; ic++) acc[jr][ic] += a[jr] * c[ic];
        }
        __syncthreads();
    }
#pragma unroll
    for (int jr = 0; jr < 4; jr++)
#pragma unroll
        for (int ic = 0; ic < 4; ic++)
            g_attn[b][n0 + ty + 16 * jr][m0 + tx + 16 * ic] = acc[jr][ic];
}

// ---------------- 3) softmax -> bf16 hi/lo split output ----------------
__global__ __launch_bounds__(256) void k_softmax()
{
    int row = blockIdx.x;
    const float* e = &g_attn[0][0][0] + (size_t)row * 1024;
    __nv_bfloat16* oh = &g_attn_h[0][0][0] + (size_t)row * 1024;
    __nv_bfloat16* ol = &g_attn_l[0][0][0] + (size_t)row * 1024;
    int tid = threadIdx.x;
    float v[4];
    float m = -3.4e38f;
#pragma unroll
    for (int j = 0; j < 4; j++) { v[j] = e[tid + 256 * j]; m = fmaxf(m, v[j]); }
    __shared__ float red[8];
#pragma unroll
    for (int o = 16; o > 0; o >>= 1) m = fmaxf(m, __shfl_xor_sync(0xffffffffu, m, o));
    if ((tid & 31) == 0) red[tid >> 5] = m;
    __syncthreads();
    m = red[0];
#pragma unroll
    for (int j = 1; j < 8; j++) m = fmaxf(m, red[j]);
    float s = 0.f;
#pragma unroll
    for (int j = 0; j < 4; j++) { v[j] = __expf(v[j] - m); s += v[j]; }
    __syncthreads();
#pragma unroll
    for (int o = 16; o > 0; o >>= 1) s += __shfl_xor_sync(0xffffffffu, s, o);
    if ((tid & 31) == 0) red[tid >> 5] = s;
    __syncthreads();
    s = red[0];
#pragma unroll
    for (int j = 1; j < 8; j++) s += red[j];
    float inv = 1.f / s;
#pragma unroll
    for (int j = 0; j < 4; j++) {
        float a = v[j] * inv;
        __nv_bfloat16 hi = __float2bfloat16(a);
        __nv_bfloat16 lo = __float2bfloat16(a - __bfloat162float(hi));
        oh[tid + 256 * j] = hi;
        ol[tid + 256 * j] = lo;
    }
}

// ---------------- 4) CAM energy partials (K-split 16) ----------------
__global__ __launch_bounds__(256) void k_came(const float* __restrict__ x)
{
    int d0 = blockIdx.x * 64;
    int c0 = blockIdx.y * 64;
    int b  = blockIdx.z >> 4;
    int sl = blockIdx.z & 15;
    __shared__ float Xc[64][33];
    __shared__ float Xd[64][33];
    int tid = threadIdx.x;
    int tx = tid & 15, ty = tid >> 4;
    float acc[4][4] = {};
    const float* xb = x + (size_t)b * (CC * NPOS);
    int n_lo = sl * 512;

    for (int nc = n_lo; nc < n_lo + 512; nc += 32) {
#pragma unroll
        for (int q = 0; q < 8; q++) {
            int e = tid + q * 256;
            int i = e >> 5, k = e & 31;
            Xc[i][k] = xb[(size_t)(c0 + i) * NPOS + nc + k];
            Xd[i][k] = xb[(size_t)(d0 + i) * NPOS + nc + k];
        }
        __syncthreads();
#pragma unroll
        for (int k = 0; k < 32; k++) {
            float a[4], c[4];
#pragma unroll
            for (int j = 0; j < 4; j++) a[j] = Xc[ty + 16 * j][k];
#pragma unroll
            for (int j = 0; j < 4; j++) c[j] = Xd[tx + 16 * j][k];
#pragma unroll
            for (int jr = 0; jr < 4; jr++)
#pragma unroll
                for (int ic = 0; ic < 4; ic++) acc[jr][ic] += a[jr] * c[ic];
        }
        __syncthreads();
    }
#pragma unroll
    for (int jr = 0; jr < 4; jr++)
#pragma unroll
        for (int ic = 0; ic < 4; ic++)
            g_ecam_p[sl][b][c0 + ty + 16 * jr][d0 + tx + 16 * ic] = acc[jr][ic];
}

// ---------------- 5) CAM negated-energy softmax ----------------
__global__ __launch_bounds__(128) void k_camsm()
{
    int b = blockIdx.x >> 7;
    int c = blockIdx.x & 127;
    int d = threadIdx.x;
    float ev = 0.f;
#pragma unroll
    for (int sl = 0; sl < 16; sl++) ev += g_ecam_p[sl][b][c][d];
    __shared__ float red[4];
    float mn = ev;
#pragma unroll
    for (int o = 16; o > 0; o >>= 1) mn = fminf(mn, __shfl_xor_sync(0xffffffffu, mn, o));
    if ((threadIdx.x & 31) == 0) red[threadIdx.x >> 5] = mn;
    __syncthreads();
    mn = fminf(fminf(red[0], red[1]), fminf(red[2], red[3]));
    float w = __expf(mn - ev);
    __syncthreads();
    float s = w;
#pragma unroll
    for (int o = 16; o > 0; o >>= 1) s += __shfl_xor_sync(0xffffffffu, s, o);
    if ((threadIdx.x & 31) == 0) red[threadIdx.x >> 5] = s;
    __syncthreads();
    s = (red[0] + red[1]) + (red[2] + red[3]);
    g_acam[b][c][d] = w / s;
}

// ---------------- 6) TIM Gram partials ----------------
__global__ __launch_bounds__(256) void k_time(const float* __restrict__ x)
{
    int c = blockIdx.x;
    int b = blockIdx.y;
    int tid = threadIdx.x;
    const float* xp = x + ((size_t)b * CC + c) * NPOS;
    float v[8][4];
#pragma unroll
    for (int t = 0; t < 8; t++) {
        float4 f = *reinterpret_cast<const float4*>(xp + t * 1024 + tid * 4);
        v[t][0] = f.x; v[t][1] = f.y; v[t][2] = f.z; v[t][3] = f.w;
    }
    float acc[36];
    int idx = 0;
#pragma unroll
    for (int t = 0; t < 8; t++)
#pragma unroll
        for (int s = t; s < 8; s++) {
            float a = 0.f;
#pragma unroll
            for (int j = 0; j < 4; j++) a += v[t][j] * v[s][j];
            acc[idx++] = a;
        }
    __shared__ float red[36][8];
    int lane = tid & 31, warp = tid >> 5;
#pragma unroll
    for (int i = 0; i < 36; i++) {
        float a = acc[i];
#pragma unroll
        for (int o = 16; o > 0; o >>= 1) a += __shfl_xor_sync(0xffffffffu, a, o);
        if (lane == 0) red[i][warp] = a;
    }
    __syncthreads();
    if (tid < 36) {
        float a = 0.f;
#pragma unroll
        for (int w = 0; w < 8; w++) a += red[tid][w];
        g_etim_p[b][c][tid] = a;
    }
}

// ---------------- 7) TIM reduce + softmax ----------------
__global__ __launch_bounds__(256) void k_timsm()
{
    __shared__ float e36[BB][36];
    int tid = threadIdx.x;
    for (int o = tid; o < BB * 36; o += 256) {
        int b = o / 36, i = o % 36;
        float a = 0.f;
        for (int c = 0; c < CC; c++) a += g_etim_p[b][c][i];
        e36[b][i] = a;
    }
    __syncthreads();
    if (tid < 64) {
        int b = tid >> 3, t = tid & 7;
        float e[8];
#pragma unroll
        for (int s = 0; s < 8; s++) {
            int lo = t < s ? t : s, hi = t < s ? s : t;
            int idx = 8 * lo - lo * (lo - 1) / 2 + (hi - lo);
            e[s] = e36[b][idx];
        }
        float mn = e[0];
#pragma unroll
        for (int s = 1; s < 8; s++) mn = fminf(mn, e[s]);
        float w[8], sum = 0.f;
#pragma unroll
        for (int s = 0; s < 8; s++) { w[s] = __expf(mn - e[s]); sum += w[s]; }
#pragma unroll
        for (int s = 0; s < 8; s++) g_atim[b][t][s] = w[s] / sum;
    }
}

// ---------------- 8) base: out = 3x + gc*(a_cam@xc) + gt*tim, all-t tiling ----------------
__global__ __launch_bounds__(256) void k_base(
    const float* __restrict__ x,
    const float* __restrict__ gcp, const float* __restrict__ gtp,
    float* __restrict__ out)
{
    int b   = blockIdx.z;
    int c0  = blockIdx.y * 32;
    int hw0 = blockIdx.x * 32;
    __shared__ float As[32][33];
    __shared__ float Xs[32][8][33];
    __shared__ float at8[8][8];
    int tid = threadIdx.x;
    int hw_l = tid & 31, cg = tid >> 5;
    if (tid < 64) at8[tid >> 3][tid & 7] = g_atim[b][tid >> 3][tid & 7];
    float acc[4][8] = {};
    const float* xb = x + (size_t)b * (CC * NPOS);

    for (int kc = 0; kc < CC; kc += 32) {
#pragma unroll
        for (int q = 0; q < 4; q++) {
            int e = tid + q * 256;
            int i = e >> 5, k = e & 31;
            As[i][k] = g_acam[b][c0 + i][kc + k];
        }
#pragma unroll
        for (int q = 0; q < 32; q++) {
            int e = tid + q * 256;
            int k = e >> 8, t = (e >> 5) & 7, hw = e & 31;
            Xs[k][t][hw] = xb[(size_t)(kc + k) * NPOS + t * 1024 + hw0 + hw];
        }
        __syncthreads();
#pragma unroll
        for (int k = 0; k < 32; k++) {
            float av[4], xv[8];
#pragma unroll
            for (int j = 0; j < 4; j++) av[j] = As[cg + 8 * j][k];
#pragma unroll
            for (int t = 0; t < 8; t++) xv[t] = Xs[k][t][hw_l];
#pragma unroll
            for (int j = 0; j < 4; j++)
#pragma unroll
                for (int t = 0; t < 8; t++) acc[j][t] += av[j] * xv[t];
        }
        __syncthreads();
    }

    float gc = gcp[0], gt = gtp[0];
#pragma unroll
    for (int j = 0; j < 4; j++) {
        int c = c0 + cg + 8 * j;
        const float* xc = xb + (size_t)c * NPOS + hw0 + hw_l;
        float xrow[8];
#pragma unroll
        for (int s = 0; s < 8; s++) xrow[s] = xc[s * 1024];
        float* oc = out + (size_t)b * (CC * NPOS) + (size_t)c * NPOS + hw0 + hw_l;
#pragma unroll
        for (int t = 0; t < 8; t++) {
            float tim = 0.f;
#pragma unroll
            for (int s = 0; s < 8; s++) tim += at8[t][s] * xrow[s];
            oc[t * 1024] = 3.f * xrow[t] + gc * acc[j][t] + gt * tim;
        }
    }
}

// ---------------- 9) PAM GEMM via mma.sync bf16x3: out += gp * (vf @ attn^T) ----------------
// CTA tile 128x128, 8 warps of 64x32, K chunk 32. NT layout (both k-contiguous).
#define PAD 40   // smem row stride in bf16 (20 words -> conflict-free lane pattern)
__global__ __launch_bounds__(256) void k_pam_mma(const float* __restrict__ gpp,
                                                 float* __restrict__ out)
{
    __shared__ __nv_bfloat16 sAh[128 * PAD];
    __shared__ __nv_bfloat16 sAl[128 * PAD];
    __shared__ __nv_bfloat16 sBh[128 * PAD];
    __shared__ __nv_bfloat16 sBl[128 * PAD];

    int tid = threadIdx.x;
    int b  = blockIdx.z;
    int r0 = blockIdx.y * 128;
    int n0 = blockIdx.x * 128;
    int wid = tid >> 5, lane = tid & 31;
    int gid = lane >> 2, tq = lane & 3;
    int wm = (wid & 1) * 64;    // m offset of warp tile
    int wn = (wid >> 1) * 32;   // n offset of warp tile

    const __nv_bfloat16* Ahp = &g_vf_h[b][0][0];
    const __nv_bfloat16* Alp = &g_vf_l[b][0][0];
    const __nv_bfloat16* Bhp = &g_attn_h[b][0][0];
    const __nv_bfloat16* Blp = &g_attn_l[b][0][0];

    float acc[4][4][4] = {};

    for (int kc = 0; kc < 1024; kc += 32) {
        // load 4 tiles of 128 rows x 32 bf16 (each row: 4x uint4)
#pragma unroll
        for (int q = 0; q < 2; q++) {
            int e = tid + q * 256;             // 0..511
            int row = e >> 2, c4 = e & 3;
            size_t go = (size_t)(r0 + row) * 1024 + kc + c4 * 8;
            uint32_t so = row * PAD + c4 * 8;
            *(uint4*)&sAh[so] = *(const uint4*)(Ahp + go);
            *(uint4*)&sAl[so] = *(const uint4*)(Alp + go);
            size_t gob = (size_t)(n0 + row) * 1024 + kc + c4 * 8;
            *(uint4*)&sBh[so] = *(const uint4*)(Bhp + gob);
            *(uint4*)&sBl[so] = *(const uint4*)(Blp + gob);
        }
        __syncthreads();

#pragma unroll
        for (int ks = 0; ks < 32; ks += 16) {
            uint32_t Af[4][4], Alf[4][4], Bf[4][2], Blf[4][2];
            int col = ks + tq * 2;
#pragma unroll
            for (int i = 0; i < 4; i++) {
                int row = wm + 16 * i + gid;
                Af[i][0]  = *(const uint32_t*)&sAh[row * PAD + col];
                Af[i][1]  = *(const uint32_t*)&sAh[(row + 8) * PAD + col];
                Af[i][2]  = *(const uint32_t*)&sAh[row * PAD + col + 8];
                Af[i][3]  = *(const uint32_t*)&sAh[(row + 8) * PAD + col + 8];
                Alf[i][0] = *(const uint32_t*)&sAl[row * PAD + col];
                Alf[i][1] = *(const uint32_t*)&sAl[(row + 8) * PAD + col];
                Alf[i][2] = *(const uint32_t*)&sAl[row * PAD + col + 8];
                Alf[i][3] = *(const uint32_t*)&sAl[(row + 8) * PAD + col + 8];
            }
#pragma unroll
            for (int j = 0; j < 4; j++) {
                int nrow = wn + 8 * j + gid;
                Bf[j][0]  = *(const uint32_t*)&sBh[nrow * PAD + col];
                Bf[j][1]  = *(const uint32_t*)&sBh[nrow * PAD + col + 8];
                Blf[j][0] = *(const uint32_t*)&sBl[nrow * PAD + col];
                Blf[j][1] = *(const uint32_t*)&sBl[nrow * PAD + col + 8];
            }
#pragma unroll
            for (int i = 0; i < 4; i++)
#pragma unroll
                for (int j = 0; j < 4; j++) {
                    mma16816(acc[i][j], Af[i],  Bf[j]);
                    mma16816(acc[i][j], Af[i],  Blf[j]);
                    mma16816(acc[i][j], Alf[i], Bf[j]);
                }
        }
        __syncthreads();
    }

    float gpv = gpp[0];
    float* ob = out + (size_t)b * (CT * HWD);
#pragma unroll
    for (int i = 0; i < 4; i++) {
#pragma unroll
        for (int j = 0; j < 4; j++) {
            int r = r0 + wm + 16 * i + gid;
            int n = n0 + wn + 8 * j + tq * 2;
            float2* p0 = (float2*)(ob + (size_t)r * 1024 + n);
            float2 v0 = *p0;
            v0.x += gpv * acc[i][j][0];
            v0.y += gpv * acc[i][j][1];
            *p0 = v0;
            float2* p1 = (float2*)(ob + (size_t)(r + 8) * 1024 + n);
            float2 v1 = *p1;
            v1.x += gpv * acc[i][j][2];
            v1.y += gpv * acc[i][j][3];
            *p1 = v1;
        }
    }
}

// ---------------- launch ----------------
extern "C" void kernel_launch(void* const* d_in, const int* in_sizes, int n_in,
                              void* d_out, int out_size)
{
    const float* x  = (const float*)d_in[0];
    const float* Wq = (const float*)d_in[1];
    const float* bq = (const float*)d_in[2];
    const float* Wk = (const float*)d_in[3];
    const float* bk = (const float*)d_in[4];
    const float* Wv = (const float*)d_in[5];
    const float* bv = (const float*)d_in[6];
    const float* gp = (const float*)d_in[7];
    const float* gc = (const float*)d_in[8];
    const float* gt = (const float*)d_in[9];
    float* out = (float*)d_out;

    k_qkv<<<dim3(64, 3, 8), 256>>>(x, Wq, bq, Wk, bk, Wv, bv);
    k_energy<<<dim3(16, 16, 8), 256>>>();
    k_softmax<<<8192, 256>>>();
    k_came<<<dim3(2, 2, 128), 256>>>(x);
    k_camsm<<<1024, 128>>>();
    k_time<<<dim3(128, 8), 256>>>(x);
    k_timsm<<<1, 256>>>();
    k_base<<<dim3(32, 4, 8), 256>>>(x, gc, gt, out);
    k_pam_mma<<<dim3(8, 8, 8), 256>>>(gp, out);
}

// round 4
// speedup vs baseline: 2.0641x; 1.3356x over previous
#include <cuda_runtime.h>
#include <cuda_bf16.h>
#include <math.h>
#include <stdint.h>

#define BB 8
#define CC 128
#define TT 8
#define HWD 1024
#define NPOS 8192
#define CT 1024

// ---------------- scratch ----------------
__device__ float g_qf[BB][128][HWD];
__device__ float g_kf[BB][128][HWD];
__device__ __nv_bfloat16 g_vf_h[BB][CT][HWD];
__device__ __nv_bfloat16 g_vf_l[BB][CT][HWD];
__device__ float g_attn[BB][HWD][HWD];
__device__ __nv_bfloat16 g_attn_h[BB][HWD][HWD];
__device__ __nv_bfloat16 g_attn_l[BB][HWD][HWD];
__device__ float g_ecam_p[16][BB][CC][CC];
__device__ float g_acam[BB][CC][CC];
__device__ float g_etim_p[BB][CC][36];
__device__ float g_atim[BB][TT][TT];

// ---------------- mma helpers ----------------
__device__ __forceinline__ void mma16816(float* c, const uint32_t* a, const uint32_t* b) {
    asm volatile(
        "mma.sync.aligned.m16n8k16.row.col.f32.bf16.bf16.f32 "
        "{%0,%1,%2,%3}, {%4,%5,%6,%7}, {%8,%9}, {%0,%1,%2,%3};"
        : "+f"(c[0]), "+f"(c[1]), "+f"(c[2]), "+f"(c[3])
        : "r"(a[0]), "r"(a[1]), "r"(a[2]), "r"(a[3]), "r"(b[0]), "r"(b[1]));
}
__device__ __forceinline__ void mma_tf32(float* c, const uint32_t* a, const uint32_t* b) {
    asm volatile(
        "mma.sync.aligned.m16n8k8.row.col.f32.tf32.tf32.f32 "
        "{%0,%1,%2,%3}, {%4,%5,%6,%7}, {%8,%9}, {%0,%1,%2,%3};"
        : "+f"(c[0]), "+f"(c[1]), "+f"(c[2]), "+f"(c[3])
        : "r"(a[0]), "r"(a[1]), "r"(a[2]), "r"(a[3]), "r"(b[0]), "r"(b[1]));
}
__device__ __forceinline__ uint32_t f2tf32(float a) {
    uint32_t r; asm("cvt.rna.tf32.f32 %0, %1;" : "=r"(r) : "f"(a)); return r;
}
__device__ __forceinline__ void split_tf32(float a, float& h, float& l) {
    uint32_t hu = f2tf32(a);
    h = __uint_as_float(hu);
    l = __uint_as_float(f2tf32(a - h));
}
__device__ __forceinline__ void split4(float4 v, float4& h, float4& l) {
    split_tf32(v.x, h.x, l.x);
    split_tf32(v.y, h.y, l.y);
    split_tf32(v.z, h.z, l.z);
    split_tf32(v.w, h.w, l.w);
}
__device__ __forceinline__ uint32_t f2u(float a) { return __float_as_uint(a); }

// ---------------- 1) fused q/k/v projection via tf32 MMA ----------------
// A = W rows (swizzled smem), B = x natural [c][pos] (pad 136).
// CTA: 64 W-rows (y-tile) x 128 pos; 8 warps (4 m x 2 n), warp tile 16x64; K=128 chunk 32.
#define QKV_SMEM_BYTES ((2048 * 2 + 32 * 136 * 2) * 4)
__global__ __launch_bounds__(256) void k_qkv_tc(
    const float* __restrict__ x,
    const float* __restrict__ Wq, const float* __restrict__ bq,
    const float* __restrict__ Wk, const float* __restrict__ bk,
    const float* __restrict__ Wv, const float* __restrict__ bv)
{
    extern __shared__ float dsm[];
    float* Wh = dsm;                   // 64x32 swizzled
    float* Wl = dsm + 2048;
    float* Bh = dsm + 4096;            // 32 x 136
    float* Bl = dsm + 4096 + 32 * 136;

    int b     = blockIdx.z;
    int rows0 = blockIdx.y * 64;
    int pos0  = blockIdx.x * 128;
    int tid = threadIdx.x, wid = tid >> 5, lane = tid & 31;
    int gid = lane >> 2, tq = lane & 3;
    int wm = (wid >> 1) * 16;
    int wn = (wid & 1) * 64;
    const float* xb = x + (size_t)b * (CC * NPOS);

    float acc[8][4] = {};

    for (int kc = 0; kc < 128; kc += 32) {
        // W tile 64 rows x 32 k, swizzled
#pragma unroll
        for (int q = 0; q < 2; q++) {
            int e = tid + q * 256;
            int row = e >> 3, c4 = e & 7;
            int r = rows0 + row;
            float4 v = make_float4(0.f, 0.f, 0.f, 0.f);
            if (r < 16)       v = *(const float4*)(Wq + r * 128 + kc + c4 * 4);
            else if (r < 32)  v = *(const float4*)(Wk + (r - 16) * 128 + kc + c4 * 4);
            else if (r < 160) v = *(const float4*)(Wv + (r - 32) * 128 + kc + c4 * 4);
            float4 h, l; split4(v, h, l);
            int so = row * 32 + ((c4 * 4) ^ ((row & 7) * 4));
            *(float4*)&Wh[so] = h;
            *(float4*)&Wl[so] = l;
        }
        // x tile 32 k-rows x 128 pos, natural, pad 136
#pragma unroll
        for (int q = 0; q < 4; q++) {
            int e = tid + q * 256;
            int f = e >> 5, ng = e & 31;
            float4 v = *(const float4*)(xb + (size_t)(kc + f) * NPOS + pos0 + ng * 4);
            float4 h, l; split4(v, h, l);
            *(float4*)&Bh[f * 136 + ng * 4] = h;
            *(float4*)&Bl[f * 136 + ng * 4] = l;
        }
        __syncthreads();
#pragma unroll
        for (int kk = 0; kk < 32; kk += 8) {
            uint32_t Af[4], Alf[4], Bf[8][2], Blf[8][2];
            int r0 = wm + gid, r1 = r0 + 8;
            int cA0 = kk + tq, cA1 = kk + tq + 4;
            Af[0]  = f2u(Wh[r0 * 32 + (cA0 ^ ((r0 & 7) * 4))]);
            Af[1]  = f2u(Wh[r1 * 32 + (cA0 ^ ((r1 & 7) * 4))]);
            Af[2]  = f2u(Wh[r0 * 32 + (cA1 ^ ((r0 & 7) * 4))]);
            Af[3]  = f2u(Wh[r1 * 32 + (cA1 ^ ((r1 & 7) * 4))]);
            Alf[0] = f2u(Wl[r0 * 32 + (cA0 ^ ((r0 & 7) * 4))]);
            Alf[1] = f2u(Wl[r1 * 32 + (cA0 ^ ((r1 & 7) * 4))]);
            Alf[2] = f2u(Wl[r0 * 32 + (cA1 ^ ((r0 & 7) * 4))]);
            Alf[3] = f2u(Wl[r1 * 32 + (cA1 ^ ((r1 & 7) * 4))]);
#pragma unroll
            for (int j = 0; j < 8; j++) {
                int n = wn + 8 * j + gid;
                Bf[j][0]  = f2u(Bh[(kk + tq) * 136 + n]);
                Bf[j][1]  = f2u(Bh[(kk + tq + 4) * 136 + n]);
                Blf[j][0] = f2u(Bl[(kk + tq) * 136 + n]);
                Blf[j][1] = f2u(Bl[(kk + tq + 4) * 136 + n]);
            }
#pragma unroll
            for (int j = 0; j < 8; j++) {
                mma_tf32(acc[j], Af,  Bf[j]);
                mma_tf32(acc[j], Af,  Blf[j]);
                mma_tf32(acc[j], Alf, Bf[j]);
            }
        }
        __syncthreads();
    }

    int t   = pos0 >> 10;
    int hw0 = pos0 & 1023;
#pragma unroll
    for (int j = 0; j < 8; j++) {
        int hw = hw0 + wn + 8 * j + 2 * tq;
#pragma unroll
        for (int half = 0; half < 2; half++) {
            int r = rows0 + wm + gid + half * 8;
            if (r >= 160) continue;
            float v0 = acc[j][half * 2 + 0];
            float v1 = acc[j][half * 2 + 1];
            if (r < 16) {
                float bias = bq[r];
                *(float2*)&g_qf[b][r * TT + t][hw] = make_float2(v0 + bias, v1 + bias);
            } else if (r < 32) {
                float bias = bk[r - 16];
                *(float2*)&g_kf[b][(r - 16) * TT + t][hw] = make_float2(v0 + bias, v1 + bias);
            } else {
                float bias = bv[r - 32];
                float a0 = v0 + bias, a1 = v1 + bias;
                __nv_bfloat16 h0 = __float2bfloat16(a0);
                __nv_bfloat16 l0 = __float2bfloat16(a0 - __bfloat162float(h0));
                __nv_bfloat16 h1 = __float2bfloat16(a1);
                __nv_bfloat16 l1 = __float2bfloat16(a1 - __bfloat162float(h1));
                int row = (r - 32) * TT + t;
                uint32_t hp = ((uint32_t)__bfloat16_as_ushort(h1) << 16) | __bfloat16_as_ushort(h0);
                uint32_t lp = ((uint32_t)__bfloat16_as_ushort(l1) << 16) | __bfloat16_as_ushort(l0);
                *(uint32_t*)&g_vf_h[b][row][hw] = hp;
                *(uint32_t*)&g_vf_l[b][row][hw] = lp;
            }
        }
    }
}

// ---------------- 2) PAM energy via tf32 MMA: E[n][m] = sum_f qf[f][n] kf[f][m] ----------------
// Both operands natural [f][.] layout, pad 136. CTA 128n x 128m, warps 4x2 (32x64), K=128 chunk 32.
#define EN_SMEM_BYTES (4 * 32 * 136 * 4)
__global__ __launch_bounds__(256) void k_energy_tc()
{
    extern __shared__ float dsm[];
    float* Ah = dsm;                    // qf tile hi
    float* Al = dsm + 32 * 136;
    float* Bh = dsm + 2 * 32 * 136;     // kf tile hi
    float* Bl = dsm + 3 * 32 * 136;

    int b  = blockIdx.z;
    int n0 = blockIdx.y * 128;
    int m0 = blockIdx.x * 128;
    int tid = threadIdx.x, wid = tid >> 5, lane = tid & 31;
    int gid = lane >> 2, tq = lane & 3;
    int wm = (wid >> 1) * 32;   // n-dim
    int wn = (wid & 1) * 64;    // m-dim

    float acc[2][8][4] = {};

    for (int kc = 0; kc < 128; kc += 32) {
#pragma unroll
        for (int q = 0; q < 4; q++) {
            int e = tid + q * 256;
            int f = e >> 5, ng = e & 31;
            float4 va = *(const float4*)(&g_qf[b][kc + f][n0 + ng * 4]);
            float4 vb = *(const float4*)(&g_kf[b][kc + f][m0 + ng * 4]);
            float4 h, l;
            split4(va, h, l);
            *(float4*)&Ah[f * 136 + ng * 4] = h;
            *(float4*)&Al[f * 136 + ng * 4] = l;
            split4(vb, h, l);
            *(float4*)&Bh[f * 136 + ng * 4] = h;
            *(float4*)&Bl[f * 136 + ng * 4] = l;
        }
        __syncthreads();
#pragma unroll
        for (int kk = 0; kk < 32; kk += 8) {
            uint32_t Af[2][4], Alf[2][4], Bf[8][2], Blf[8][2];
#pragma unroll
            for (int i = 0; i < 2; i++) {
                int m = wm + 16 * i + gid;
                Af[i][0]  = f2u(Ah[(kk + tq) * 136 + m]);
                Af[i][1]  = f2u(Ah[(kk + tq) * 136 + m + 8]);
                Af[i][2]  = f2u(Ah[(kk + tq + 4) * 136 + m]);
                Af[i][3]  = f2u(Ah[(kk + tq + 4) * 136 + m + 8]);
                Alf[i][0] = f2u(Al[(kk + tq) * 136 + m]);
                Alf[i][1] = f2u(Al[(kk + tq) * 136 + m + 8]);
                Alf[i][2] = f2u(Al[(kk + tq + 4) * 136 + m]);
                Alf[i][3] = f2u(Al[(kk + tq + 4) * 136 + m + 8]);
            }
#pragma unroll
            for (int j = 0; j < 8; j++) {
                int n = wn + 8 * j + gid;
                Bf[j][0]  = f2u(Bh[(kk + tq) * 136 + n]);
                Bf[j][1]  = f2u(Bh[(kk + tq + 4) * 136 + n]);
                Blf[j][0] = f2u(Bl[(kk + tq) * 136 + n]);
                Blf[j][1] = f2u(Bl[(kk + tq + 4) * 136 + n]);
            }
#pragma unroll
            for (int i = 0; i < 2; i++)
#pragma unroll
                for (int j = 0; j < 8; j++) {
                    mma_tf32(acc[i][j], Af[i],  Bf[j]);
                    mma_tf32(acc[i][j], Af[i],  Blf[j]);
                    mma_tf32(acc[i][j], Alf[i], Bf[j]);
                }
        }
        __syncthreads();
    }

#pragma unroll
    for (int i = 0; i < 2; i++)
#pragma unroll
        for (int j = 0; j < 8; j++) {
            int n = n0 + wm + 16 * i + gid;
            int m = m0 + wn + 8 * j + 2 * tq;
            *(float2*)&g_attn[b][n][m]     = make_float2(acc[i][j][0], acc[i][j][1]);
            *(float2*)&g_attn[b][n + 8][m] = make_float2(acc[i][j][2], acc[i][j][3]);
        }
}

// ---------------- 3) softmax -> bf16 hi/lo ----------------
__global__ __launch_bounds__(256) void k_softmax()
{
    int row = blockIdx.x;
    const float* e = &g_attn[0][0][0] + (size_t)row * 1024;
    __nv_bfloat16* oh = &g_attn_h[0][0][0] + (size_t)row * 1024;
    __nv_bfloat16* ol = &g_attn_l[0][0][0] + (size_t)row * 1024;
    int tid = threadIdx.x;
    float v[4];
    float m = -3.4e38f;
#pragma unroll
    for (int j = 0; j < 4; j++) { v[j] = e[tid + 256 * j]; m = fmaxf(m, v[j]); }
    __shared__ float red[8];
#pragma unroll
    for (int o = 16; o > 0; o >>= 1) m = fmaxf(m, __shfl_xor_sync(0xffffffffu, m, o));
    if ((tid & 31) == 0) red[tid >> 5] = m;
    __syncthreads();
    m = red[0];
#pragma unroll
    for (int j = 1; j < 8; j++) m = fmaxf(m, red[j]);
    float s = 0.f;
#pragma unroll
    for (int j = 0; j < 4; j++) { v[j] = __expf(v[j] - m); s += v[j]; }
    __syncthreads();
#pragma unroll
    for (int o = 16; o > 0; o >>= 1) s += __shfl_xor_sync(0xffffffffu, s, o);
    if ((tid & 31) == 0) red[tid >> 5] = s;
    __syncthreads();
    s = red[0];
#pragma unroll
    for (int j = 1; j < 8; j++) s += red[j];
    float inv = 1.f / s;
#pragma unroll
    for (int j = 0; j < 4; j++) {
        float a = v[j] * inv;
        __nv_bfloat16 hi = __float2bfloat16(a);
        __nv_bfloat16 lo = __float2bfloat16(a - __bfloat162float(hi));
        oh[tid + 256 * j] = hi;
        ol[tid + 256 * j] = lo;
    }
}

// ---------------- 4) CAM energy via tf32 MMA Gram (K-split 16) ----------------
// One swizzled buffer serves A and B. CTA computes full 128x128 for one (b, slice).
__global__ __launch_bounds__(256) void k_came_tc(const float* __restrict__ x)
{
    __shared__ float Xh[128 * 32];
    __shared__ float Xl[128 * 32];
    int b  = blockIdx.x >> 4;
    int sl = blockIdx.x & 15;
    int tid = threadIdx.x, wid = tid >> 5, lane = tid & 31;
    int gid = lane >> 2, tq = lane & 3;
    int wm = (wid >> 1) * 32;
    int wn = (wid & 1) * 64;
    const float* xb = x + (size_t)b * (CC * NPOS) + sl * 512;

    float acc[2][8][4] = {};

    for (int kc = 0; kc < 512; kc += 32) {
#pragma unroll
        for (int q = 0; q < 4; q++) {
            int e = tid + q * 256;
            int row = e >> 3, c4 = e & 7;
            float4 v = *(const float4*)(xb + (size_t)row * NPOS + kc + c4 * 4);
            float4 h, l; split4(v, h, l);
            int so = row * 32 + ((c4 * 4) ^ ((row & 7) * 4));
            *(float4*)&Xh[so] = h;
            *(float4*)&Xl[so] = l;
        }
        __syncthreads();
#pragma unroll
        for (int kk = 0; kk < 32; kk += 8) {
            uint32_t Af[2][4], Alf[2][4], Bf[8][2], Blf[8][2];
            int c0 = kk + tq, c1 = kk + tq + 4;
#pragma unroll
            for (int i = 0; i < 2; i++) {
                int r0 = wm + 16 * i + gid, r1 = r0 + 8;
                Af[i][0]  = f2u(Xh[r0 * 32 + (c0 ^ ((r0 & 7) * 4))]);
                Af[i][1]  = f2u(Xh[r1 * 32 + (c0 ^ ((r1 & 7) * 4))]);
                Af[i][2]  = f2u(Xh[r0 * 32 + (c1 ^ ((r0 & 7) * 4))]);
                Af[i][3]  = f2u(Xh[r1 * 32 + (c1 ^ ((r1 & 7) * 4))]);
                Alf[i][0] = f2u(Xl[r0 * 32 + (c0 ^ ((r0 & 7) * 4))]);
                Alf[i][1] = f2u(Xl[r1 * 32 + (c0 ^ ((r1 & 7) * 4))]);
                Alf[i][2] = f2u(Xl[r0 * 32 + (c1 ^ ((r0 & 7) * 4))]);
                Alf[i][3] = f2u(Xl[r1 * 32 + (c1 ^ ((r1 & 7) * 4))]);
            }
#pragma unroll
            for (int j = 0; j < 8; j++) {
                int rn = wn + 8 * j + gid;
                Bf[j][0]  = f2u(Xh[rn * 32 + (c0 ^ ((rn & 7) * 4))]);
                Bf[j][1]  = f2u(Xh[rn * 32 + (c1 ^ ((rn & 7) * 4))]);
                Blf[j][0] = f2u(Xl[rn * 32 + (c0 ^ ((rn & 7) * 4))]);
                Blf[j][1] = f2u(Xl[rn * 32 + (c1 ^ ((rn & 7) * 4))]);
            }
#pragma unroll
            for (int i = 0; i < 2; i++)
#pragma unroll
                for (int j = 0; j < 8; j++) {
                    mma_tf32(acc[i][j], Af[i],  Bf[j]);
                    mma_tf32(acc[i][j], Af[i],  Blf[j]);
                    mma_tf32(acc[i][j], Alf[i], Bf[j]);
                }
        }
        __syncthreads();
    }

#pragma unroll
    for (int i = 0; i < 2; i++)
#pragma unroll
        for (int j = 0; j < 8; j++) {
            int c = wm + 16 * i + gid;
            int d = wn + 8 * j + 2 * tq;
            *(float2*)&g_ecam_p[sl][b][c][d]     = make_float2(acc[i][j][0], acc[i][j][1]);
            *(float2*)&g_ecam_p[sl][b][c + 8][d] = make_float2(acc[i][j][2], acc[i][j][3]);
        }
}

// ---------------- 5) CAM negated-energy softmax ----------------
__global__ __launch_bounds__(128) void k_camsm()
{
    int b = blockIdx.x >> 7;
    int c = blockIdx.x & 127;
    int d = threadIdx.x;
    float ev = 0.f;
#pragma unroll
    for (int sl = 0; sl < 16; sl++) ev += g_ecam_p[sl][b][c][d];
    __shared__ float red[4];
    float mn = ev;
#pragma unroll
    for (int o = 16; o > 0; o >>= 1) mn = fminf(mn, __shfl_xor_sync(0xffffffffu, mn, o));
    if ((threadIdx.x & 31) == 0) red[threadIdx.x >> 5] = mn;
    __syncthreads();
    mn = fminf(fminf(red[0], red[1]), fminf(red[2], red[3]));
    float w = __expf(mn - ev);
    __syncthreads();
    float s = w;
#pragma unroll
    for (int o = 16; o > 0; o >>= 1) s += __shfl_xor_sync(0xffffffffu, s, o);
    if ((threadIdx.x & 31) == 0) red[threadIdx.x >> 5] = s;
    __syncthreads();
    s = (red[0] + red[1]) + (red[2] + red[3]);
    g_acam[b][c][d] = w / s;
}

// ---------------- 6) TIM Gram partials ----------------
__global__ __launch_bounds__(256) void k_time(const float* __restrict__ x)
{
    int c = blockIdx.x;
    int b = blockIdx.y;
    int tid = threadIdx.x;
    const float* xp = x + ((size_t)b * CC + c) * NPOS;
    float v[8][4];
#pragma unroll
    for (int t = 0; t < 8; t++) {
        float4 f = *reinterpret_cast<const float4*>(xp + t * 1024 + tid * 4);
        v[t][0] = f.x; v[t][1] = f.y; v[t][2] = f.z; v[t][3] = f.w;
    }
    float acc[36];
    int idx = 0;
#pragma unroll
    for (int t = 0; t < 8; t++)
#pragma unroll
        for (int s = t; s < 8; s++) {
            float a = 0.f;
#pragma unroll
            for (int j = 0; j < 4; j++) a += v[t][j] * v[s][j];
            acc[idx++] = a;
        }
    __shared__ float red[36][8];
    int lane = tid & 31, warp = tid >> 5;
#pragma unroll
    for (int i = 0; i < 36; i++) {
        float a = acc[i];
#pragma unroll
        for (int o = 16; o > 0; o >>= 1) a += __shfl_xor_sync(0xffffffffu, a, o);
        if (lane == 0) red[i][warp] = a;
    }
    __syncthreads();
    if (tid < 36) {
        float a = 0.f;
#pragma unroll
        for (int w = 0; w < 8; w++) a += red[tid][w];
        g_etim_p[b][c][tid] = a;
    }
}

// ---------------- 7) TIM reduce + softmax ----------------
__global__ __launch_bounds__(256) void k_timsm()
{
    __shared__ float e36[BB][36];
    int tid = threadIdx.x;
    for (int o = tid; o < BB * 36; o += 256) {
        int b = o / 36, i = o % 36;
        float a = 0.f;
        for (int c = 0; c < CC; c++) a += g_etim_p[b][c][i];
        e36[b][i] = a;
    }
    __syncthreads();
    if (tid < 64) {
        int b = tid >> 3, t = tid & 7;
        float e[8];
#pragma unroll
        for (int s = 0; s < 8; s++) {
            int lo = t < s ? t : s, hi = t < s ? s : t;
            int idx = 8 * lo - lo * (lo - 1) / 2 + (hi - lo);
            e[s] = e36[b][idx];
        }
        float mn = e[0];
#pragma unroll
        for (int s = 1; s < 8; s++) mn = fminf(mn, e[s]);
        float w[8], sum = 0.f;
#pragma unroll
        for (int s = 0; s < 8; s++) { w[s] = __expf(mn - e[s]); sum += w[s]; }
#pragma unroll
        for (int s = 0; s < 8; s++) g_atim[b][t][s] = w[s] / sum;
    }
}

// ---------------- 8) base: out = 3x + gc*(a_cam@xc) + gt*tim ----------------
__global__ __launch_bounds__(256) void k_base(
    const float* __restrict__ x,
    const float* __restrict__ gcp, const float* __restrict__ gtp,
    float* __restrict__ out)
{
    int b   = blockIdx.z;
    int c0  = blockIdx.y * 32;
    int hw0 = blockIdx.x * 32;
    __shared__ float As[32][33];
    __shared__ float Xs[32][8][33];
    __shared__ float at8[8][8];
    int tid = threadIdx.x;
    int hw_l = tid & 31, cg = tid >> 5;
    if (tid < 64) at8[tid >> 3][tid & 7] = g_atim[b][tid >> 3][tid & 7];
    float acc[4][8] = {};
    const float* xb = x + (size_t)b * (CC * NPOS);

    for (int kc = 0; kc < CC; kc += 32) {
#pragma unroll
        for (int q = 0; q < 4; q++) {
            int e = tid + q * 256;
            int i = e >> 5, k = e & 31;
            As[i][k] = g_acam[b][c0 + i][kc + k];
        }
#pragma unroll
        for (int q = 0; q < 32; q++) {
            int e = tid + q * 256;
            int k = e >> 8, t = (e >> 5) & 7, hw = e & 31;
            Xs[k][t][hw] = xb[(size_t)(kc + k) * NPOS + t * 1024 + hw0 + hw];
        }
        __syncthreads();
#pragma unroll
        for (int k = 0; k < 32; k++) {
            float av[4], xv[8];
#pragma unroll
            for (int j = 0; j < 4; j++) av[j] = As[cg + 8 * j][k];
#pragma unroll
            for (int t = 0; t < 8; t++) xv[t] = Xs[k][t][hw_l];
#pragma unroll
            for (int j = 0; j < 4; j++)
#pragma unroll
                for (int t = 0; t < 8; t++) acc[j][t] += av[j] * xv[t];
        }
        __syncthreads();
    }

    float gc = gcp[0], gt = gtp[0];
#pragma unroll
    for (int j = 0; j < 4; j++) {
        int c = c0 + cg + 8 * j;
        const float* xc = xb + (size_t)c * NPOS + hw0 + hw_l;
        float xrow[8];
#pragma unroll
        for (int s = 0; s < 8; s++) xrow[s] = xc[s * 1024];
        float* oc = out + (size_t)b * (CC * NPOS) + (size_t)c * NPOS + hw0 + hw_l;
#pragma unroll
        for (int t = 0; t < 8; t++) {
            float tim = 0.f;
#pragma unroll
            for (int s = 0; s < 8; s++) tim += at8[t][s] * xrow[s];
            oc[t * 1024] = 3.f * xrow[t] + gc * acc[j][t] + gt * tim;
        }
    }
}

// ---------------- 9) PAM GEMM via mma.sync bf16x3 ----------------
#define PAD 40
__global__ __launch_bounds__(256) void k_pam_mma(const float* __restrict__ gpp,
                                                 float* __restrict__ out)
{
    __shared__ __nv_bfloat16 sAh[128 * PAD];
    __shared__ __nv_bfloat16 sAl[128 * PAD];
    __shared__ __nv_bfloat16 sBh[128 * PAD];
    __shared__ __nv_bfloat16 sBl[128 * PAD];

    int tid = threadIdx.x;
    int b  = blockIdx.z;
    int r0 = blockIdx.y * 128;
    int n0 = blockIdx.x * 128;
    int wid = tid >> 5, lane = tid & 31;
    int gid = lane >> 2, tq = lane & 3;
    int wm = (wid & 1) * 64;
    int wn = (wid >> 1) * 32;

    const __nv_bfloat16* Ahp = &g_vf_h[b][0][0];
    const __nv_bfloat16* Alp = &g_vf_l[b][0][0];
    const __nv_bfloat16* Bhp = &g_attn_h[b][0][0];
    const __nv_bfloat16* Blp = &g_attn_l[b][0][0];

    float acc[4][4][4] = {};

    for (int kc = 0; kc < 1024; kc += 32) {
#pragma unroll
        for (int q = 0; q < 2; q++) {
            int e = tid + q * 256;
            int row = e >> 2, c4 = e & 3;
            size_t go = (size_t)(r0 + row) * 1024 + kc + c4 * 8;
            uint32_t so = row * PAD + c4 * 8;
            *(uint4*)&sAh[so] = *(const uint4*)(Ahp + go);
            *(uint4*)&sAl[so] = *(const uint4*)(Alp + go);
            size_t gob = (size_t)(n0 + row) * 1024 + kc + c4 * 8;
            *(uint4*)&sBh[so] = *(const uint4*)(Bhp + gob);
            *(uint4*)&sBl[so] = *(const uint4*)(Blp + gob);
        }
        __syncthreads();

#pragma unroll
        for (int ks = 0; ks < 32; ks += 16) {
            uint32_t Af[4][4], Alf[4][4], Bf[4][2], Blf[4][2];
            int col = ks + tq * 2;
#pragma unroll
            for (int i = 0; i < 4; i++) {
                int row = wm + 16 * i + gid;
                Af[i][0]  = *(const uint32_t*)&sAh[row * PAD + col];
                Af[i][1]  = *(const uint32_t*)&sAh[(row + 8) * PAD + col];
                Af[i][2]  = *(const uint32_t*)&sAh[row * PAD + col + 8];
                Af[i][3]  = *(const uint32_t*)&sAh[(row + 8) * PAD + col + 8];
                Alf[i][0] = *(const uint32_t*)&sAl[row * PAD + col];
                Alf[i][1] = *(const uint32_t*)&sAl[(row + 8) * PAD + col];
                Alf[i][2] = *(const uint32_t*)&sAl[row * PAD + col + 8];
                Alf[i][3] = *(const uint32_t*)&sAl[(row + 8) * PAD + col + 8];
            }
#pragma unroll
            for (int j = 0; j < 4; j++) {
                int nrow = wn + 8 * j + gid;
                Bf[j][0]  = *(const uint32_t*)&sBh[nrow * PAD + col];
                Bf[j][1]  = *(const uint32_t*)&sBh[nrow * PAD + col + 8];
                Blf[j][0] = *(const uint32_t*)&sBl[nrow * PAD + col];
                Blf[j][1] = *(const uint32_t*)&sBl[nrow * PAD + col + 8];
            }
#pragma unroll
            for (int i = 0; i < 4; i++)
#pragma unroll
                for (int j = 0; j < 4; j++) {
                    mma16816(acc[i][j], Af[i],  Bf[j]);
                    mma16816(acc[i][j], Af[i],  Blf[j]);
                    mma16816(acc[i][j], Alf[i], Bf[j]);
                }
        }
        __syncthreads();
    }

    float gpv = gpp[0];
    float* ob = out + (size_t)b * (CT * HWD);
#pragma unroll
    for (int i = 0; i < 4; i++) {
#pragma unroll
        for (int j = 0; j < 4; j++) {
            int r = r0 + wm + 16 * i + gid;
            int n = n0 + wn + 8 * j + tq * 2;
            float2* p0 = (float2*)(ob + (size_t)r * 1024 + n);
            float2 v0 = *p0;
            v0.x += gpv * acc[i][j][0];
            v0.y += gpv * acc[i][j][1];
            *p0 = v0;
            float2* p1 = (float2*)(ob + (size_t)(r + 8) * 1024 + n);
            float2 v1 = *p1;
            v1.x += gpv * acc[i][j][2];
            v1.y += gpv * acc[i][j][3];
            *p1 = v1;
        }
    }
}

// ---------------- launch ----------------
extern "C" void kernel_launch(void* const* d_in, const int* in_sizes, int n_in,
                              void* d_out, int out_size)
{
    const float* x  = (const float*)d_in[0];
    const float* Wq = (const float*)d_in[1];
    const float* bq = (const float*)d_in[2];
    const float* Wk = (const float*)d_in[3];
    const float* bk = (const float*)d_in[4];
    const float* Wv = (const float*)d_in[5];
    const float* bv = (const float*)d_in[6];
    const float* gp = (const float*)d_in[7];
    const float* gc = (const float*)d_in[8];
    const float* gt = (const float*)d_in[9];
    float* out = (float*)d_out;

    static int attrs_set = 0;
    if (!attrs_set) {
        cudaFuncSetAttribute(k_qkv_tc, cudaFuncAttributeMaxDynamicSharedMemorySize, QKV_SMEM_BYTES);
        cudaFuncSetAttribute(k_energy_tc, cudaFuncAttributeMaxDynamicSharedMemorySize, EN_SMEM_BYTES);
        attrs_set = 1;
    }

    k_qkv_tc<<<dim3(64, 3, 8), 256, QKV_SMEM_BYTES>>>(x, Wq, bq, Wk, bk, Wv, bv);
    k_energy_tc<<<dim3(8, 8, 8), 256, EN_SMEM_BYTES>>>();
    k_softmax<<<8192, 256>>>();
    k_came_tc<<<128, 256>>>(x);
    k_camsm<<<1024, 128>>>();
    k_time<<<dim3(128, 8), 256>>>(x);
    k_timsm<<<1, 256>>>();
    k_base<<<dim3(32, 4, 8), 256>>>(x, gc, gt, out);
    k_pam_mma<<<dim3(8, 8, 8), 256>>>(gp, out);
}

// round 5
// speedup vs baseline: 2.2452x; 1.0877x over previous
#include <cuda_runtime.h>
#include <cuda_bf16.h>
#include <math.h>
#include <stdint.h>

#define BB 8
#define CC 128
#define TT 8
#define HWD 1024
#define NPOS 8192
#define CT 1024

// ---------------- scratch ----------------
__device__ float g_qf[BB][128][HWD];
__device__ float g_kf[BB][128][HWD];
__device__ __nv_bfloat16 g_vf_h[BB][CT][HWD];
__device__ __nv_bfloat16 g_vf_l[BB][CT][HWD];
__device__ float g_attn[BB][HWD][HWD];
__device__ __nv_bfloat16 g_attn_h[BB][HWD][HWD];
__device__ __nv_bfloat16 g_attn_l[BB][HWD][HWD];
__device__ float g_ecam_p[32][BB][CC][CC];
__device__ float g_acam[BB][CC][CC];
__device__ float g_etim_p[BB][CC][36];
__device__ float g_atim[BB][TT][TT];

// ---------------- mma / cp.async helpers ----------------
__device__ __forceinline__ void mma16816(float* c, const uint32_t* a, const uint32_t* b) {
    asm volatile(
        "mma.sync.aligned.m16n8k16.row.col.f32.bf16.bf16.f32 "
        "{%0,%1,%2,%3}, {%4,%5,%6,%7}, {%8,%9}, {%0,%1,%2,%3};"
        : "+f"(c[0]), "+f"(c[1]), "+f"(c[2]), "+f"(c[3])
        : "r"(a[0]), "r"(a[1]), "r"(a[2]), "r"(a[3]), "r"(b[0]), "r"(b[1]));
}
__device__ __forceinline__ void mma_tf32(float* c, const uint32_t* a, const uint32_t* b) {
    asm volatile(
        "mma.sync.aligned.m16n8k8.row.col.f32.tf32.tf32.f32 "
        "{%0,%1,%2,%3}, {%4,%5,%6,%7}, {%8,%9}, {%0,%1,%2,%3};"
        : "+f"(c[0]), "+f"(c[1]), "+f"(c[2]), "+f"(c[3])
        : "r"(a[0]), "r"(a[1]), "r"(a[2]), "r"(a[3]), "r"(b[0]), "r"(b[1]));
}
__device__ __forceinline__ uint32_t f2tf32(float a) {
    uint32_t r; asm("cvt.rna.tf32.f32 %0, %1;" : "=r"(r) : "f"(a)); return r;
}
__device__ __forceinline__ void split_tf32(float a, float& h, float& l) {
    uint32_t hu = f2tf32(a);
    h = __uint_as_float(hu);
    l = __uint_as_float(f2tf32(a - h));
}
__device__ __forceinline__ void split4(float4 v, float4& h, float4& l) {
    split_tf32(v.x, h.x, l.x);
    split_tf32(v.y, h.y, l.y);
    split_tf32(v.z, h.z, l.z);
    split_tf32(v.w, h.w, l.w);
}
__device__ __forceinline__ uint32_t f2u(float a) { return __float_as_uint(a); }
__device__ __forceinline__ uint32_t smem_to_u32(const void* p) {
    uint32_t a;
    asm("{ .reg .u64 t; cvta.to.shared.u64 t, %1; cvt.u32.u64 %0, t; }" : "=r"(a) : "l"(p));
    return a;
}
__device__ __forceinline__ void cp16(uint32_t s, const void* g) {
    asm volatile("cp.async.cg.shared.global [%0], [%1], 16;"
                 :: "r"(s), "l"(__cvta_generic_to_global(g)) : "memory");
}

// ---------------- 1) fused q/k/v projection via tf32 MMA ----------------
#define QKV_SMEM_BYTES ((2048 * 2 + 32 * 136 * 2) * 4)
__global__ __launch_bounds__(256) void k_qkv_tc(
    const float* __restrict__ x,
    const float* __restrict__ Wq, const float* __restrict__ bq,
    const float* __restrict__ Wk, const float* __restrict__ bk,
    const float* __restrict__ Wv, const float* __restrict__ bv)
{
    extern __shared__ float dsm[];
    float* Wh = dsm;
    float* Wl = dsm + 2048;
    float* Bh = dsm + 4096;
    float* Bl = dsm + 4096 + 32 * 136;

    int b     = blockIdx.z;
    int rows0 = blockIdx.y * 64;
    int pos0  = blockIdx.x * 128;
    int tid = threadIdx.x, wid = tid >> 5, lane = tid & 31;
    int gid = lane >> 2, tq = lane & 3;
    int wm = (wid >> 1) * 16;
    int wn = (wid & 1) * 64;
    const float* xb = x + (size_t)b * (CC * NPOS);

    float acc[8][4] = {};

    for (int kc = 0; kc < 128; kc += 32) {
#pragma unroll
        for (int q = 0; q < 2; q++) {
            int e = tid + q * 256;
            int row = e >> 3, c4 = e & 7;
            int r = rows0 + row;
            float4 v = make_float4(0.f, 0.f, 0.f, 0.f);
            if (r < 16)       v = *(const float4*)(Wq + r * 128 + kc + c4 * 4);
            else if (r < 32)  v = *(const float4*)(Wk + (r - 16) * 128 + kc + c4 * 4);
            else if (r < 160) v = *(const float4*)(Wv + (r - 32) * 128 + kc + c4 * 4);
            float4 h, l; split4(v, h, l);
            int so = row * 32 + ((c4 * 4) ^ ((row & 7) * 4));
            *(float4*)&Wh[so] = h;
            *(float4*)&Wl[so] = l;
        }
#pragma unroll
        for (int q = 0; q < 4; q++) {
            int e = tid + q * 256;
            int f = e >> 5, ng = e & 31;
            float4 v = *(const float4*)(xb + (size_t)(kc + f) * NPOS + pos0 + ng * 4);
            float4 h, l; split4(v, h, l);
            *(float4*)&Bh[f * 136 + ng * 4] = h;
            *(float4*)&Bl[f * 136 + ng * 4] = l;
        }
        __syncthreads();
#pragma unroll
        for (int kk = 0; kk < 32; kk += 8) {
            uint32_t Af[4], Alf[4];
            int r0 = wm + gid, r1 = r0 + 8;
            int cA0 = kk + tq, cA1 = kk + tq + 4;
            Af[0]  = f2u(Wh[r0 * 32 + (cA0 ^ ((r0 & 7) * 4))]);
            Af[1]  = f2u(Wh[r1 * 32 + (cA0 ^ ((r1 & 7) * 4))]);
            Af[2]  = f2u(Wh[r0 * 32 + (cA1 ^ ((r0 & 7) * 4))]);
            Af[3]  = f2u(Wh[r1 * 32 + (cA1 ^ ((r1 & 7) * 4))]);
            Alf[0] = f2u(Wl[r0 * 32 + (cA0 ^ ((r0 & 7) * 4))]);
            Alf[1] = f2u(Wl[r1 * 32 + (cA0 ^ ((r1 & 7) * 4))]);
            Alf[2] = f2u(Wl[r0 * 32 + (cA1 ^ ((r0 & 7) * 4))]);
            Alf[3] = f2u(Wl[r1 * 32 + (cA1 ^ ((r1 & 7) * 4))]);
#pragma unroll
            for (int j = 0; j < 8; j++) {
                int n = wn + 8 * j + gid;
                uint32_t Bf[2], Blf[2];
                Bf[0]  = f2u(Bh[(kk + tq) * 136 + n]);
                Bf[1]  = f2u(Bh[(kk + tq + 4) * 136 + n]);
                Blf[0] = f2u(Bl[(kk + tq) * 136 + n]);
                Blf[1] = f2u(Bl[(kk + tq + 4) * 136 + n]);
                mma_tf32(acc[j], Af,  Bf);
                mma_tf32(acc[j], Af,  Blf);
                mma_tf32(acc[j], Alf, Bf);
            }
        }
        __syncthreads();
    }

    int t   = pos0 >> 10;
    int hw0 = pos0 & 1023;
#pragma unroll
    for (int j = 0; j < 8; j++) {
        int hw = hw0 + wn + 8 * j + 2 * tq;
#pragma unroll
        for (int half = 0; half < 2; half++) {
            int r = rows0 + wm + gid + half * 8;
            if (r >= 160) continue;
            float v0 = acc[j][half * 2 + 0];
            float v1 = acc[j][half * 2 + 1];
            if (r < 16) {
                float bias = bq[r];
                *(float2*)&g_qf[b][r * TT + t][hw] = make_float2(v0 + bias, v1 + bias);
            } else if (r < 32) {
                float bias = bk[r - 16];
                *(float2*)&g_kf[b][(r - 16) * TT + t][hw] = make_float2(v0 + bias, v1 + bias);
            } else {
                float bias = bv[r - 32];
                float a0 = v0 + bias, a1 = v1 + bias;
                __nv_bfloat16 h0 = __float2bfloat16(a0);
                __nv_bfloat16 l0 = __float2bfloat16(a0 - __bfloat162float(h0));
                __nv_bfloat16 h1 = __float2bfloat16(a1);
                __nv_bfloat16 l1 = __float2bfloat16(a1 - __bfloat162float(h1));
                int row = (r - 32) * TT + t;
                uint32_t hp = ((uint32_t)__bfloat16_as_ushort(h1) << 16) | __bfloat16_as_ushort(h0);
                uint32_t lp = ((uint32_t)__bfloat16_as_ushort(l1) << 16) | __bfloat16_as_ushort(l0);
                *(uint32_t*)&g_vf_h[b][row][hw] = hp;
                *(uint32_t*)&g_vf_l[b][row][hw] = lp;
            }
        }
    }
}

// ---------------- 2) PAM energy via tf32 MMA ----------------
#define EN_SMEM_BYTES (4 * 32 * 136 * 4)
__global__ __launch_bounds__(256, 2) void k_energy_tc()
{
    extern __shared__ float dsm[];
    float* Ah = dsm;
    float* Al = dsm + 32 * 136;
    float* Bh = dsm + 2 * 32 * 136;
    float* Bl = dsm + 3 * 32 * 136;

    int b  = blockIdx.z;
    int n0 = blockIdx.y * 128;
    int m0 = blockIdx.x * 128;
    int tid = threadIdx.x, wid = tid >> 5, lane = tid & 31;
    int gid = lane >> 2, tq = lane & 3;
    int wm = (wid >> 1) * 32;
    int wn = (wid & 1) * 64;

    float acc[2][8][4] = {};

    for (int kc = 0; kc < 128; kc += 32) {
#pragma unroll
        for (int q = 0; q < 4; q++) {
            int e = tid + q * 256;
            int f = e >> 5, ng = e & 31;
            float4 va = *(const float4*)(&g_qf[b][kc + f][n0 + ng * 4]);
            float4 vb = *(const float4*)(&g_kf[b][kc + f][m0 + ng * 4]);
            float4 h, l;
            split4(va, h, l);
            *(float4*)&Ah[f * 136 + ng * 4] = h;
            *(float4*)&Al[f * 136 + ng * 4] = l;
            split4(vb, h, l);
            *(float4*)&Bh[f * 136 + ng * 4] = h;
            *(float4*)&Bl[f * 136 + ng * 4] = l;
        }
        __syncthreads();
#pragma unroll
        for (int kk = 0; kk < 32; kk += 8) {
            uint32_t Af[2][4], Alf[2][4];
#pragma unroll
            for (int i = 0; i < 2; i++) {
                int m = wm + 16 * i + gid;
                Af[i][0]  = f2u(Ah[(kk + tq) * 136 + m]);
                Af[i][1]  = f2u(Ah[(kk + tq) * 136 + m + 8]);
                Af[i][2]  = f2u(Ah[(kk + tq + 4) * 136 + m]);
                Af[i][3]  = f2u(Ah[(kk + tq + 4) * 136 + m + 8]);
                Alf[i][0] = f2u(Al[(kk + tq) * 136 + m]);
                Alf[i][1] = f2u(Al[(kk + tq) * 136 + m + 8]);
                Alf[i][2] = f2u(Al[(kk + tq + 4) * 136 + m]);
                Alf[i][3] = f2u(Al[(kk + tq + 4) * 136 + m + 8]);
            }
#pragma unroll
            for (int j = 0; j < 8; j++) {
                int n = wn + 8 * j + gid;
                uint32_t Bf[2], Blf[2];
                Bf[0]  = f2u(Bh[(kk + tq) * 136 + n]);
                Bf[1]  = f2u(Bh[(kk + tq + 4) * 136 + n]);
                Blf[0] = f2u(Bl[(kk + tq) * 136 + n]);
                Blf[1] = f2u(Bl[(kk + tq + 4) * 136 + n]);
#pragma unroll
                for (int i = 0; i < 2; i++) {
                    mma_tf32(acc[i][j], Af[i],  Bf);
                    mma_tf32(acc[i][j], Af[i],  Blf);
                    mma_tf32(acc[i][j], Alf[i], Bf);
                }
            }
        }
        __syncthreads();
    }

#pragma unroll
    for (int i = 0; i < 2; i++)
#pragma unroll
        for (int j = 0; j < 8; j++) {
            int n = n0 + wm + 16 * i + gid;
            int m = m0 + wn + 8 * j + 2 * tq;
            *(float2*)&g_attn[b][n][m]     = make_float2(acc[i][j][0], acc[i][j][1]);
            *(float2*)&g_attn[b][n + 8][m] = make_float2(acc[i][j][2], acc[i][j][3]);
        }
}

// ---------------- 3) softmax -> bf16 hi/lo ----------------
__global__ __launch_bounds__(256) void k_softmax()
{
    int row = blockIdx.x;
    const float* e = &g_attn[0][0][0] + (size_t)row * 1024;
    __nv_bfloat16* oh = &g_attn_h[0][0][0] + (size_t)row * 1024;
    __nv_bfloat16* ol = &g_attn_l[0][0][0] + (size_t)row * 1024;
    int tid = threadIdx.x;
    float v[4];
    float m = -3.4e38f;
#pragma unroll
    for (int j = 0; j < 4; j++) { v[j] = e[tid + 256 * j]; m = fmaxf(m, v[j]); }
    __shared__ float red[8];
#pragma unroll
    for (int o = 16; o > 0; o >>= 1) m = fmaxf(m, __shfl_xor_sync(0xffffffffu, m, o));
    if ((tid & 31) == 0) red[tid >> 5] = m;
    __syncthreads();
    m = red[0];
#pragma unroll
    for (int j = 1; j < 8; j++) m = fmaxf(m, red[j]);
    float s = 0.f;
#pragma unroll
    for (int j = 0; j < 4; j++) { v[j] = __expf(v[j] - m); s += v[j]; }
    __syncthreads();
#pragma unroll
    for (int o = 16; o > 0; o >>= 1) s += __shfl_xor_sync(0xffffffffu, s, o);
    if ((tid & 31) == 0) red[tid >> 5] = s;
    __syncthreads();
    s = red[0];
#pragma unroll
    for (int j = 1; j < 8; j++) s += red[j];
    float inv = 1.f / s;
#pragma unroll
    for (int j = 0; j < 4; j++) {
        float a = v[j] * inv;
        __nv_bfloat16 hi = __float2bfloat16(a);
        __nv_bfloat16 lo = __float2bfloat16(a - __bfloat162float(hi));
        oh[tid + 256 * j] = hi;
        ol[tid + 256 * j] = lo;
    }
}

// ---------------- 4) CAM energy via tf32 MMA Gram (K-split 32) ----------------
__global__ __launch_bounds__(256, 2) void k_came_tc(const float* __restrict__ x)
{
    __shared__ float Xh[128 * 32];
    __shared__ float Xl[128 * 32];
    int b  = blockIdx.x >> 5;
    int sl = blockIdx.x & 31;
    int tid = threadIdx.x, wid = tid >> 5, lane = tid & 31;
    int gid = lane >> 2, tq = lane & 3;
    int wm = (wid >> 1) * 32;
    int wn = (wid & 1) * 64;
    const float* xb = x + (size_t)b * (CC * NPOS) + sl * 256;

    float acc[2][8][4] = {};

    for (int kc = 0; kc < 256; kc += 32) {
#pragma unroll
        for (int q = 0; q < 4; q++) {
            int e = tid + q * 256;
            int row = e >> 3, c4 = e & 7;
            float4 v = *(const float4*)(xb + (size_t)row * NPOS + kc + c4 * 4);
            float4 h, l; split4(v, h, l);
            int so = row * 32 + ((c4 * 4) ^ ((row & 7) * 4));
            *(float4*)&Xh[so] = h;
            *(float4*)&Xl[so] = l;
        }
        __syncthreads();
#pragma unroll
        for (int kk = 0; kk < 32; kk += 8) {
            uint32_t Af[2][4], Alf[2][4];
            int c0 = kk + tq, c1 = kk + tq + 4;
#pragma unroll
            for (int i = 0; i < 2; i++) {
                int r0 = wm + 16 * i + gid, r1 = r0 + 8;
                Af[i][0]  = f2u(Xh[r0 * 32 + (c0 ^ ((r0 & 7) * 4))]);
                Af[i][1]  = f2u(Xh[r1 * 32 + (c0 ^ ((r1 & 7) * 4))]);
                Af[i][2]  = f2u(Xh[r0 * 32 + (c1 ^ ((r0 & 7) * 4))]);
                Af[i][3]  = f2u(Xh[r1 * 32 + (c1 ^ ((r1 & 7) * 4))]);
                Alf[i][0] = f2u(Xl[r0 * 32 + (c0 ^ ((r0 & 7) * 4))]);
                Alf[i][1] = f2u(Xl[r1 * 32 + (c0 ^ ((r1 & 7) * 4))]);
                Alf[i][2] = f2u(Xl[r0 * 32 + (c1 ^ ((r0 & 7) * 4))]);
                Alf[i][3] = f2u(Xl[r1 * 32 + (c1 ^ ((r1 & 7) * 4))]);
            }
#pragma unroll
            for (int j = 0; j < 8; j++) {
                int rn = wn + 8 * j + gid;
                uint32_t Bf[2], Blf[2];
                Bf[0]  = f2u(Xh[rn * 32 + (c0 ^ ((rn & 7) * 4))]);
                Bf[1]  = f2u(Xh[rn * 32 + (c1 ^ ((rn & 7) * 4))]);
                Blf[0] = f2u(Xl[rn * 32 + (c0 ^ ((rn & 7) * 4))]);
                Blf[1] = f2u(Xl[rn * 32 + (c1 ^ ((rn & 7) * 4))]);
#pragma unroll
                for (int i = 0; i < 2; i++) {
                    mma_tf32(acc[i][j], Af[i],  Bf);
                    mma_tf32(acc[i][j], Af[i],  Blf);
                    mma_tf32(acc[i][j], Alf[i], Bf);
                }
            }
        }
        __syncthreads();
    }

#pragma unroll
    for (int i = 0; i < 2; i++)
#pragma unroll
        for (int j = 0; j < 8; j++) {
            int c = wm + 16 * i + gid;
            int d = wn + 8 * j + 2 * tq;
            *(float2*)&g_ecam_p[sl][b][c][d]     = make_float2(acc[i][j][0], acc[i][j][1]);
            *(float2*)&g_ecam_p[sl][b][c + 8][d] = make_float2(acc[i][j][2], acc[i][j][3]);
        }
}

// ---------------- 5) CAM negated-energy softmax ----------------
__global__ __launch_bounds__(128) void k_camsm()
{
    int b = blockIdx.x >> 7;
    int c = blockIdx.x & 127;
    int d = threadIdx.x;
    float ev = 0.f;
#pragma unroll
    for (int sl = 0; sl < 32; sl++) ev += g_ecam_p[sl][b][c][d];
    __shared__ float red[4];
    float mn = ev;
#pragma unroll
    for (int o = 16; o > 0; o >>= 1) mn = fminf(mn, __shfl_xor_sync(0xffffffffu, mn, o));
    if ((threadIdx.x & 31) == 0) red[threadIdx.x >> 5] = mn;
    __syncthreads();
    mn = fminf(fminf(red[0], red[1]), fminf(red[2], red[3]));
    float w = __expf(mn - ev);
    __syncthreads();
    float s = w;
#pragma unroll
    for (int o = 16; o > 0; o >>= 1) s += __shfl_xor_sync(0xffffffffu, s, o);
    if ((threadIdx.x & 31) == 0) red[threadIdx.x >> 5] = s;
    __syncthreads();
    s = (red[0] + red[1]) + (red[2] + red[3]);
    g_acam[b][c][d] = w / s;
}

// ---------------- 6) TIM Gram partials ----------------
__global__ __launch_bounds__(256) void k_time(const float* __restrict__ x)
{
    int c = blockIdx.x;
    int b = blockIdx.y;
    int tid = threadIdx.x;
    const float* xp = x + ((size_t)b * CC + c) * NPOS;
    float v[8][4];
#pragma unroll
    for (int t = 0; t < 8; t++) {
        float4 f = *reinterpret_cast<const float4*>(xp + t * 1024 + tid * 4);
        v[t][0] = f.x; v[t][1] = f.y; v[t][2] = f.z; v[t][3] = f.w;
    }
    float acc[36];
    int idx = 0;
#pragma unroll
    for (int t = 0; t < 8; t++)
#pragma unroll
        for (int s = t; s < 8; s++) {
            float a = 0.f;
#pragma unroll
            for (int j = 0; j < 4; j++) a += v[t][j] * v[s][j];
            acc[idx++] = a;
        }
    __shared__ float red[36][8];
    int lane = tid & 31, warp = tid >> 5;
#pragma unroll
    for (int i = 0; i < 36; i++) {
        float a = acc[i];
#pragma unroll
        for (int o = 16; o > 0; o >>= 1) a += __shfl_xor_sync(0xffffffffu, a, o);
        if (lane == 0) red[i][warp] = a;
    }
    __syncthreads();
    if (tid < 36) {
        float a = 0.f;
#pragma unroll
        for (int w = 0; w < 8; w++) a += red[tid][w];
        g_etim_p[b][c][tid] = a;
    }
}

// ---------------- 7) TIM reduce + softmax ----------------
__global__ __launch_bounds__(256) void k_timsm()
{
    __shared__ float e36[BB][36];
    int tid = threadIdx.x;
    for (int o = tid; o < BB * 36; o += 256) {
        int b = o / 36, i = o % 36;
        float a = 0.f;
        for (int c = 0; c < CC; c++) a += g_etim_p[b][c][i];
        e36[b][i] = a;
    }
    __syncthreads();
    if (tid < 64) {
        int b = tid >> 3, t = tid & 7;
        float e[8];
#pragma unroll
        for (int s = 0; s < 8; s++) {
            int lo = t < s ? t : s, hi = t < s ? s : t;
            int idx = 8 * lo - lo * (lo - 1) / 2 + (hi - lo);
            e[s] = e36[b][idx];
        }
        float mn = e[0];
#pragma unroll
        for (int s = 1; s < 8; s++) mn = fminf(mn, e[s]);
        float w[8], sum = 0.f;
#pragma unroll
        for (int s = 0; s < 8; s++) { w[s] = __expf(mn - e[s]); sum += w[s]; }
#pragma unroll
        for (int s = 0; s < 8; s++) g_atim[b][t][s] = w[s] / sum;
    }
}

// ---------------- 8) base: out = 3x + gc*(a_cam@xc) + gt*tim ----------------
__global__ __launch_bounds__(256) void k_base(
    const float* __restrict__ x,
    const float* __restrict__ gcp, const float* __restrict__ gtp,
    float* __restrict__ out)
{
    int b   = blockIdx.z;
    int c0  = blockIdx.y * 32;
    int hw0 = blockIdx.x * 32;
    __shared__ float As[32][33];
    __shared__ float Xs[32][8][33];
    __shared__ float at8[8][8];
    int tid = threadIdx.x;
    int hw_l = tid & 31, cg = tid >> 5;
    if (tid < 64) at8[tid >> 3][tid & 7] = g_atim[b][tid >> 3][tid & 7];
    float acc[4][8] = {};
    const float* xb = x + (size_t)b * (CC * NPOS);

    for (int kc = 0; kc < CC; kc += 32) {
#pragma unroll
        for (int q = 0; q < 4; q++) {
            int e = tid + q * 256;
            int i = e >> 5, k = e & 31;
            As[i][k] = g_acam[b][c0 + i][kc + k];
        }
#pragma unroll
        for (int q = 0; q < 32; q++) {
            int e = tid + q * 256;
            int k = e >> 8, t = (e >> 5) & 7, hw = e & 31;
            Xs[k][t][hw] = xb[(size_t)(kc + k) * NPOS + t * 1024 + hw0 + hw];
        }
        __syncthreads();
#pragma unroll
        for (int k = 0; k < 32; k++) {
            float av[4], xv[8];
#pragma unroll
            for (int j = 0; j < 4; j++) av[j] = As[cg + 8 * j][k];
#pragma unroll
            for (int t = 0; t < 8; t++) xv[t] = Xs[k][t][hw_l];
#pragma unroll
            for (int j = 0; j < 4; j++)
#pragma unroll
                for (int t = 0; t < 8; t++) acc[j][t] += av[j] * xv[t];
        }
        __syncthreads();
    }

    float gc = gcp[0], gt = gtp[0];
#pragma unroll
    for (int j = 0; j < 4; j++) {
        int c = c0 + cg + 8 * j;
        const float* xc = xb + (size_t)c * NPOS + hw0 + hw_l;
        float xrow[8];
#pragma unroll
        for (int s = 0; s < 8; s++) xrow[s] = xc[s * 1024];
        float* oc = out + (size_t)b * (CC * NPOS) + (size_t)c * NPOS + hw0 + hw_l;
#pragma unroll
        for (int t = 0; t < 8; t++) {
            float tim = 0.f;
#pragma unroll
            for (int s = 0; s < 8; s++) tim += at8[t][s] * xrow[s];
            oc[t * 1024] = 3.f * xrow[t] + gc * acc[j][t] + gt * tim;
        }
    }
}

// ---------------- 9) PAM GEMM via mma.sync bf16x3, cp.async 2-stage ----------------
#define PAD 40
#define PAM_STAGE_ELTS 20480   // 4 buffers x 128*40 bf16
#define PAM_SMEM_BYTES (2 * PAM_STAGE_ELTS * 2)
__global__ __launch_bounds__(256, 2) void k_pam_mma(const float* __restrict__ gpp,
                                                    float* __restrict__ out)
{
    extern __shared__ __nv_bfloat16 smp[];
    uint32_t smb = smem_to_u32(smp);

    int tid = threadIdx.x;
    int b  = blockIdx.z;
    int r0 = blockIdx.y * 128;
    int n0 = blockIdx.x * 128;
    int wid = tid >> 5, lane = tid & 31;
    int gid = lane >> 2, tq = lane & 3;
    int wm = (wid & 1) * 64;
    int wn = (wid >> 1) * 32;

    const __nv_bfloat16* Ahp = &g_vf_h[b][0][0];
    const __nv_bfloat16* Alp = &g_vf_l[b][0][0];
    const __nv_bfloat16* Bhp = &g_attn_h[b][0][0];
    const __nv_bfloat16* Blp = &g_attn_l[b][0][0];

    float acc[4][4][4] = {};

    int lrow = 0, lc4 = 0; (void)lrow; (void)lc4;
    auto stage_load = [&](int st, int kc) {
#pragma unroll
        for (int q = 0; q < 2; q++) {
            int e = tid + q * 256;
            int row = e >> 2, c4 = e & 3;
            uint32_t so = smb + (uint32_t)(st * PAM_STAGE_ELTS + row * PAD + c4 * 8) * 2;
            size_t gA = (size_t)(r0 + row) * 1024 + kc + c4 * 8;
            size_t gB = (size_t)(n0 + row) * 1024 + kc + c4 * 8;
            cp16(so,              Ahp + gA);
            cp16(so + 5120 * 2,   Alp + gA);
            cp16(so + 10240 * 2,  Bhp + gB);
            cp16(so + 15360 * 2,  Blp + gB);
        }
        asm volatile("cp.async.commit_group;" ::: "memory");
    };

    stage_load(0, 0);

    for (int it = 0; it < 32; it++) {
        int st = it & 1;
        if (it < 31) {
            stage_load(st ^ 1, (it + 1) * 32);
            asm volatile("cp.async.wait_group 1;" ::: "memory");
        } else {
            asm volatile("cp.async.wait_group 0;" ::: "memory");
        }
        __syncthreads();

        const __nv_bfloat16* sAh = smp + st * PAM_STAGE_ELTS;
        const __nv_bfloat16* sAl = sAh + 5120;
        const __nv_bfloat16* sBh = sAh + 10240;
        const __nv_bfloat16* sBl = sAh + 15360;

#pragma unroll
        for (int ks = 0; ks < 32; ks += 16) {
            uint32_t Af[4][4], Alf[4][4];
            int col = ks + tq * 2;
#pragma unroll
            for (int i = 0; i < 4; i++) {
                int row = wm + 16 * i + gid;
                Af[i][0]  = *(const uint32_t*)&sAh[row * PAD + col];
                Af[i][1]  = *(const uint32_t*)&sAh[(row + 8) * PAD + col];
                Af[i][2]  = *(const uint32_t*)&sAh[row * PAD + col + 8];
                Af[i][3]  = *(const uint32_t*)&sAh[(row + 8) * PAD + col + 8];
                Alf[i][0] = *(const uint32_t*)&sAl[row * PAD + col];
                Alf[i][1] = *(const uint32_t*)&sAl[(row + 8) * PAD + col];
                Alf[i][2] = *(const uint32_t*)&sAl[row * PAD + col + 8];
                Alf[i][3] = *(const uint32_t*)&sAl[(row + 8) * PAD + col + 8];
            }
#pragma unroll
            for (int j = 0; j < 4; j++) {
                int nrow = wn + 8 * j + gid;
                uint32_t Bf[2], Blf[2];
                Bf[0]  = *(const uint32_t*)&sBh[nrow * PAD + col];
                Bf[1]  = *(const uint32_t*)&sBh[nrow * PAD + col + 8];
                Blf[0] = *(const uint32_t*)&sBl[nrow * PAD + col];
                Blf[1] = *(const uint32_t*)&sBl[nrow * PAD + col + 8];
#pragma unroll
                for (int i = 0; i < 4; i++) {
                    mma16816(acc[i][j], Af[i],  Bf);
                    mma16816(acc[i][j], Af[i],  Blf);
                    mma16816(acc[i][j], Alf[i], Bf);
                }
            }
        }
        __syncthreads();
    }

    float gpv = gpp[0];
    float* ob = out + (size_t)b * (CT * HWD);
#pragma unroll
    for (int i = 0; i < 4; i++) {
#pragma unroll
        for (int j = 0; j < 4; j++) {
            int r = r0 + wm + 16 * i + gid;
            int n = n0 + wn + 8 * j + tq * 2;
            float2* p0 = (float2*)(ob + (size_t)r * 1024 + n);
            float2 v0 = *p0;
            v0.x += gpv * acc[i][j][0];
            v0.y += gpv * acc[i][j][1];
            *p0 = v0;
            float2* p1 = (float2*)(ob + (size_t)(r + 8) * 1024 + n);
            float2 v1 = *p1;
            v1.x += gpv * acc[i][j][2];
            v1.y += gpv * acc[i][j][3];
            *p1 = v1;
        }
    }
}

// ---------------- launch ----------------
extern "C" void kernel_launch(void* const* d_in, const int* in_sizes, int n_in,
                              void* d_out, int out_size)
{
    const float* x  = (const float*)d_in[0];
    const float* Wq = (const float*)d_in[1];
    const float* bq = (const float*)d_in[2];
    const float* Wk = (const float*)d_in[3];
    const float* bk = (const float*)d_in[4];
    const float* Wv = (const float*)d_in[5];
    const float* bv = (const float*)d_in[6];
    const float* gp = (const float*)d_in[7];
    const float* gc = (const float*)d_in[8];
    const float* gt = (const float*)d_in[9];
    float* out = (float*)d_out;

    static int attrs_set = 0;
    if (!attrs_set) {
        cudaFuncSetAttribute(k_qkv_tc, cudaFuncAttributeMaxDynamicSharedMemorySize, QKV_SMEM_BYTES);
        cudaFuncSetAttribute(k_energy_tc, cudaFuncAttributeMaxDynamicSharedMemorySize, EN_SMEM_BYTES);
        cudaFuncSetAttribute(k_pam_mma, cudaFuncAttributeMaxDynamicSharedMemorySize, PAM_SMEM_BYTES);
        attrs_set = 1;
    }

    k_qkv_tc<<<dim3(64, 3, 8), 256, QKV_SMEM_BYTES>>>(x, Wq, bq, Wk, bk, Wv, bv);
    k_energy_tc<<<dim3(8, 8, 8), 256, EN_SMEM_BYTES>>>();
    k_softmax<<<8192, 256>>>();
    k_came_tc<<<256, 256>>>(x);
    k_camsm<<<1024, 128>>>();
    k_time<<<dim3(128, 8), 256>>>(x);
    k_timsm<<<1, 256>>>();
    k_base<<<dim3(32, 4, 8), 256>>>(x, gc, gt, out);
    k_pam_mma<<<dim3(8, 8, 8), 256, PAM_SMEM_BYTES>>>(gp, out);
}